// round 5
// baseline (speedup 1.0000x reference)
#include <cuda_runtime.h>
#include <cuda_bf16.h>
#include <math_constants.h>
#include <cstdint>
#include <cstddef>

#define S 2048
#define D 4096
#define HQ 32
#define HKV 8
#define HD 128
#define NREP 4
#define KV_W (HKV * HD) /* 1024 */

// ---------------- scratch (no allocations allowed) ----------------
__device__ float g_Q[(size_t)S * D];     // 32 MB
__device__ float g_K[(size_t)S * KV_W];  // 8 MB
__device__ float g_V[(size_t)S * KV_W];  // 8 MB
__device__ float g_A[(size_t)S * D];     // 32 MB (attention output)

// ---------------- packed f32x2 helpers (Blackwell FFMA2) ----------------
__device__ __forceinline__ unsigned long long pack2(float x, float y) {
    unsigned long long r;
    asm("mov.b64 %0, {%1, %2};" : "=l"(r)
        : "r"(__float_as_uint(x)), "r"(__float_as_uint(y)));
    return r;
}
__device__ __forceinline__ float2 unpack2(unsigned long long v) {
    unsigned int a, b;
    asm("mov.b64 {%0, %1}, %2;" : "=r"(a), "=r"(b) : "l"(v));
    return make_float2(__uint_as_float(a), __uint_as_float(b));
}
__device__ __forceinline__ void ffma2(unsigned long long& d,
                                      unsigned long long a,
                                      unsigned long long b) {
    asm("fma.rn.f32x2 %0, %1, %2, %0;" : "+l"(d) : "l"(a), "l"(b));
}
__device__ __forceinline__ void fmul2(unsigned long long& d, unsigned long long a) {
    asm("mul.rn.f32x2 %0, %0, %1;" : "+l"(d) : "l"(a));
}

// ---------------- SGEMM: C[M,N] = A[M,K] @ B[K,N], fp32, f32x2 inner ----------------
// 128x128 block tile, BK=8, 256 threads, 8x8 per thread (split 4+4).
__global__ __launch_bounds__(256) void sgemm_kernel(
    const float* __restrict__ A, const float* __restrict__ B,
    float* __restrict__ C, int M, int N, int K) {
    __shared__ float As[8][128];  // transposed: As[k][m]
    __shared__ float Bs[8][128];  // Bs[k][n]

    const int bm = blockIdx.y * 128;
    const int bn = blockIdx.x * 128;
    const int tid = threadIdx.x;

    const int arow = tid >> 1, acol = (tid & 1) << 2;   // A tile: 128 rows x 8 cols
    const int brow = tid >> 5, bcol = (tid & 31) << 2;  // B tile: 8 rows x 128 cols
    const int tx = tid & 15, ty = tid >> 4;

    unsigned long long acc[2][2][4][2];
#pragma unroll
    for (int a = 0; a < 2; a++)
#pragma unroll
        for (int b = 0; b < 2; b++)
#pragma unroll
            for (int i = 0; i < 4; i++) {
                acc[a][b][i][0] = 0ull;
                acc[a][b][i][1] = 0ull;
            }

    const float* Aptr = A + (size_t)(bm + arow) * K + acol;
    const float* Bptr = B + (size_t)brow * N + bn + bcol;

    float4 av = *(const float4*)Aptr;
    float4 bv = *(const float4*)Bptr;

    const int nk = K >> 3;
    for (int kt = 0; kt < nk; kt++) {
        As[acol + 0][arow] = av.x;
        As[acol + 1][arow] = av.y;
        As[acol + 2][arow] = av.z;
        As[acol + 3][arow] = av.w;
        *(float4*)&Bs[brow][bcol] = bv;
        __syncthreads();

        if (kt + 1 < nk) {
            av = *(const float4*)(Aptr + (size_t)(kt + 1) * 8);
            bv = *(const float4*)(Bptr + (size_t)(kt + 1) * 8 * N);
        }

#pragma unroll
        for (int k = 0; k < 8; k++) {
            float4 a0 = *(float4*)&As[k][ty * 4];
            float4 a1 = *(float4*)&As[k][ty * 4 + 64];
            ulonglong2 b0 = *(ulonglong2*)&Bs[k][tx * 4];
            ulonglong2 b1 = *(ulonglong2*)&Bs[k][tx * 4 + 64];
            float ar0[4] = {a0.x, a0.y, a0.z, a0.w};
            float ar1[4] = {a1.x, a1.y, a1.z, a1.w};
#pragma unroll
            for (int i = 0; i < 4; i++) {
                unsigned long long ad0 = pack2(ar0[i], ar0[i]);
                ffma2(acc[0][0][i][0], ad0, b0.x);
                ffma2(acc[0][0][i][1], ad0, b0.y);
                ffma2(acc[0][1][i][0], ad0, b1.x);
                ffma2(acc[0][1][i][1], ad0, b1.y);
            }
#pragma unroll
            for (int i = 0; i < 4; i++) {
                unsigned long long ad1 = pack2(ar1[i], ar1[i]);
                ffma2(acc[1][0][i][0], ad1, b0.x);
                ffma2(acc[1][0][i][1], ad1, b0.y);
                ffma2(acc[1][1][i][0], ad1, b1.x);
                ffma2(acc[1][1][i][1], ad1, b1.y);
            }
        }
        __syncthreads();
    }

#pragma unroll
    for (int si = 0; si < 2; si++)
#pragma unroll
        for (int i = 0; i < 4; i++) {
            int row = bm + si * 64 + ty * 4 + i;
#pragma unroll
            for (int sj = 0; sj < 2; sj++) {
                float2 p0 = unpack2(acc[si][sj][i][0]);
                float2 p1 = unpack2(acc[si][sj][i][1]);
                *(float4*)(C + (size_t)row * N + bn + sj * 64 + tx * 4) =
                    make_float4(p0.x, p0.y, p1.x, p1.y);
            }
        }
}

// ---------------- RoPE (interleaved pairs), in-place on Q and K ----------------
__global__ void rope_kernel(float* __restrict__ Q, float* __restrict__ K,
                            const float* __restrict__ cosv,
                            const float* __restrict__ sinv) {
    const int qn = S * HQ * (HD / 2);
    const int kn = S * HKV * (HD / 2);
    int idx = blockIdx.x * blockDim.x + threadIdx.x;
    if (idx < qn) {
        int i = idx & 63;
        int h = (idx >> 6) & (HQ - 1);
        int s = idx >> 11;
        float c = cosv[(s << 6) + i];
        float sn = sinv[(s << 6) + i];
        float2* p = (float2*)(Q + (size_t)s * D + h * HD) + i;
        float2 v = *p;
        *p = make_float2(v.x * c - v.y * sn, v.x * sn + v.y * c);
    } else if (idx < qn + kn) {
        int t = idx - qn;
        int i = t & 63;
        int h = (t >> 6) & (HKV - 1);
        int s = t >> 9;
        float c = cosv[(s << 6) + i];
        float sn = sinv[(s << 6) + i];
        float2* p = (float2*)(K + (size_t)s * KV_W + h * HD) + i;
        float2 v = *p;
        *p = make_float2(v.x * c - v.y * sn, v.x * sn + v.y * c);
    }
}

// ---------------- Flash attention, fp32, causal, GQA ----------------
// grid = (S/64, HQ), 256 threads. Dynamic smem ~114 KB.
#define BQ 64
#define BK 64
#define KT_STRIDE 68
#define PS_STRIDE 65
#define ATTN_SMEM ((BQ * HD + HD * KT_STRIDE + BK * HD + BQ * PS_STRIDE) * 4)

__global__ __launch_bounds__(256) void attn_kernel(
    const float* __restrict__ Qg, const float* __restrict__ Kg,
    const float* __restrict__ Vg, float* __restrict__ Og) {
    extern __shared__ float sm[];
    float* Qs = sm;                      // [64][128]
    float* Kt = Qs + BQ * HD;            // [128][68]  (transposed K)
    float* Vs = Kt + HD * KT_STRIDE;     // [64][128]
    float* Ps = Vs + BK * HD;            // [64][65]

    const int h = blockIdx.y;
    const int q0 = blockIdx.x * BQ;
    const int kvh = h >> 2;  // N_REP = 4
    const int tid = threadIdx.x;
    const int row = tid >> 2;  // 0..63 (PV / softmax row)
    const int lr = tid & 3;    // 4 threads per row
    const int tx = tid & 15, ty = tid >> 4;  // score 16x16 map

    // load Q tile
    for (int i = tid; i < BQ * HD / 4; i += 256) {
        int r = i >> 5, c4 = (i & 31) << 2;
        *(float4*)(Qs + r * HD + c4) =
            *(const float4*)(Qg + (size_t)(q0 + r) * D + h * HD + c4);
    }

    float m_i = -CUDART_INF_F, l_i = 0.f;
    unsigned long long o2[16];
#pragma unroll
    for (int d = 0; d < 16; d++) o2[d] = 0ull;

    const float scale = 0.08838834764831845f;  // 1/sqrt(128)

    for (int k0 = 0; k0 <= q0; k0 += BK) {
        __syncthreads();  // previous PV reads done before overwrite
        // load K (transposed) and V tiles
        for (int i = tid; i < BK * HD / 4; i += 256) {
            int r = i >> 5, c4 = (i & 31) << 2;
            float4 kv = *(const float4*)(Kg + (size_t)(k0 + r) * KV_W + kvh * HD + c4);
            Kt[(c4 + 0) * KT_STRIDE + r] = kv.x;
            Kt[(c4 + 1) * KT_STRIDE + r] = kv.y;
            Kt[(c4 + 2) * KT_STRIDE + r] = kv.z;
            Kt[(c4 + 3) * KT_STRIDE + r] = kv.w;
            *(float4*)(Vs + r * HD + c4) =
                *(const float4*)(Vg + (size_t)(k0 + r) * KV_W + kvh * HD + c4);
        }
        __syncthreads();

        // scores: each thread a 4x4 tile of S = Q K^T
        unsigned long long sc2[4][2];
#pragma unroll
        for (int i = 0; i < 4; i++) { sc2[i][0] = 0ull; sc2[i][1] = 0ull; }
#pragma unroll 4
        for (int kk = 0; kk < HD; kk++) {
            ulonglong2 b = *(ulonglong2*)(Kt + kk * KT_STRIDE + tx * 4);
#pragma unroll
            for (int i = 0; i < 4; i++) {
                float a = Qs[(ty * 4 + i) * HD + kk];
                unsigned long long ad = pack2(a, a);
                ffma2(sc2[i][0], ad, b.x);
                ffma2(sc2[i][1], ad, b.y);
            }
        }
        // mask + scale + store to Ps
#pragma unroll
        for (int i = 0; i < 4; i++) {
            int qr = q0 + ty * 4 + i;
            float2 p0 = unpack2(sc2[i][0]);
            float2 p1 = unpack2(sc2[i][1]);
            float v[4] = {p0.x, p0.y, p1.x, p1.y};
#pragma unroll
            for (int j = 0; j < 4; j++) {
                int kc = k0 + tx * 4 + j;
                Ps[(ty * 4 + i) * PS_STRIDE + tx * 4 + j] =
                    (kc <= qr) ? v[j] * scale : -CUDART_INF_F;
            }
        }
        __syncwarp();  // score writers and softmax readers of a row share a warp

        // online softmax: 4 threads per row, 16 cols each
        float* prow = Ps + row * PS_STRIDE;
        float rmax = -CUDART_INF_F;
#pragma unroll
        for (int j = 0; j < 16; j++) rmax = fmaxf(rmax, prow[lr * 16 + j]);
        rmax = fmaxf(rmax, __shfl_xor_sync(0xffffffff, rmax, 1));
        rmax = fmaxf(rmax, __shfl_xor_sync(0xffffffff, rmax, 2));
        float m_new = fmaxf(m_i, rmax);
        float rsum = 0.f;
#pragma unroll
        for (int j = 0; j < 16; j++) {
            float p = __expf(prow[lr * 16 + j] - m_new);
            prow[lr * 16 + j] = p;
            rsum += p;
        }
        rsum += __shfl_xor_sync(0xffffffff, rsum, 1);
        rsum += __shfl_xor_sync(0xffffffff, rsum, 2);
        float f = __expf(m_i - m_new);
        l_i = l_i * f + rsum;
        m_i = m_new;
        unsigned long long fd = pack2(f, f);
#pragma unroll
        for (int d = 0; d < 16; d++) fmul2(o2[d], fd);
        __syncwarp();  // all 4 row-threads' P values visible

        // PV: thread owns dims {lr*4 + 16*d : d in 0..7} of its row
#pragma unroll 2
        for (int j = 0; j < BK; j++) {
            float p = prow[j];
            unsigned long long pd = pack2(p, p);
#pragma unroll
            for (int d = 0; d < 8; d++) {
                ulonglong2 v = *(ulonglong2*)(Vs + j * HD + lr * 4 + d * 16);
                ffma2(o2[2 * d + 0], pd, v.x);
                ffma2(o2[2 * d + 1], pd, v.y);
            }
        }
    }

    float inv = 1.f / l_i;
#pragma unroll
    for (int d = 0; d < 8; d++) {
        float2 p0 = unpack2(o2[2 * d + 0]);
        float2 p1 = unpack2(o2[2 * d + 1]);
        *(float4*)(Og + (size_t)(q0 + row) * D + h * HD + lr * 4 + d * 16) =
            make_float4(p0.x * inv, p0.y * inv, p1.x * inv, p1.y * inv);
    }
}

// ---------------- launch ----------------
extern "C" void kernel_launch(void* const* d_in, const int* in_sizes, int n_in,
                              void* d_out, int out_size) {
    const float* x = (const float*)d_in[0];
    const float* wq = (const float*)d_in[1];
    const float* wk = (const float*)d_in[2];
    const float* wv = (const float*)d_in[3];
    const float* wo = (const float*)d_in[4];
    const float* cosv = (const float*)d_in[5];
    const float* sinv = (const float*)d_in[6];
    // d_in[7] = mask (unused: causal handled by index comparison)
    float* out = (float*)d_out;

    float *pQ, *pK, *pV, *pA;
    cudaGetSymbolAddress((void**)&pQ, g_Q);
    cudaGetSymbolAddress((void**)&pK, g_K);
    cudaGetSymbolAddress((void**)&pV, g_V);
    cudaGetSymbolAddress((void**)&pA, g_A);

    // opt-in large dynamic smem for attention (sticky; errors ignorable)
    cudaFuncSetAttribute(attn_kernel, cudaFuncAttributeMaxDynamicSharedMemorySize,
                         ATTN_SMEM);

    dim3 blk(256);
    // QKV projections
    sgemm_kernel<<<dim3(D / 128, S / 128), blk>>>(x, wq, pQ, S, D, D);
    sgemm_kernel<<<dim3(KV_W / 128, S / 128), blk>>>(x, wk, pK, S, KV_W, D);
    sgemm_kernel<<<dim3(KV_W / 128, S / 128), blk>>>(x, wv, pV, S, KV_W, D);

    // RoPE on Q and K
    {
        int total = S * HQ * (HD / 2) + S * HKV * (HD / 2);
        rope_kernel<<<(total + 255) / 256, 256>>>(pQ, pK, cosv, sinv);
    }

    // attention
    attn_kernel<<<dim3(S / BQ, HQ), blk, ATTN_SMEM>>>(pQ, pK, pV, pA);

    // output projection
    sgemm_kernel<<<dim3(D / 128, S / 128), blk>>>(pA, wo, out, S, D, D);
}

// round 7
// speedup vs baseline: 1.3917x; 1.3917x over previous
#include <cuda_runtime.h>
#include <cuda_bf16.h>
#include <math_constants.h>
#include <cstdint>
#include <cstddef>

#define S 2048
#define D 4096
#define HQ 32
#define HKV 8
#define HD 128
#define KV_W (HKV * HD) /* 1024 */

// ---------------- scratch (no allocations allowed) ----------------
__device__ float g_Q[(size_t)S * D];     // 32 MB
__device__ float g_K[(size_t)S * KV_W];  // 8 MB
__device__ float g_V[(size_t)S * KV_W];  // 8 MB
__device__ float g_A[(size_t)S * D];     // 32 MB (attention output)

// bf16 hi/lo split buffers
__device__ __nv_bfloat16 g_Xh[(size_t)S * D], g_Xl[(size_t)S * D];  // also reused for A
__device__ __nv_bfloat16 g_Wqh[(size_t)D * D], g_Wql[(size_t)D * D];  // transposed [N,K]
__device__ __nv_bfloat16 g_Wkh[(size_t)KV_W * D], g_Wkl[(size_t)KV_W * D];
__device__ __nv_bfloat16 g_Wvh[(size_t)KV_W * D], g_Wvl[(size_t)KV_W * D];
__device__ __nv_bfloat16 g_Woh[(size_t)D * D], g_Wol[(size_t)D * D];

// ---------------- packed f32x2 helpers (attention) ----------------
__device__ __forceinline__ unsigned long long pack2(float x, float y) {
    unsigned long long r;
    asm("mov.b64 %0, {%1, %2};" : "=l"(r)
        : "r"(__float_as_uint(x)), "r"(__float_as_uint(y)));
    return r;
}
__device__ __forceinline__ float2 unpack2(unsigned long long v) {
    unsigned int a, b;
    asm("mov.b64 {%0, %1}, %2;" : "=r"(a), "=r"(b) : "l"(v));
    return make_float2(__uint_as_float(a), __uint_as_float(b));
}
__device__ __forceinline__ void ffma2(unsigned long long& d,
                                      unsigned long long a,
                                      unsigned long long b) {
    asm("fma.rn.f32x2 %0, %1, %2, %0;" : "+l"(d) : "l"(a), "l"(b));
}
__device__ __forceinline__ void fmul2(unsigned long long& d, unsigned long long a) {
    asm("mul.rn.f32x2 %0, %0, %1;" : "+l"(d) : "l"(a));
}

// ---------------- mma.sync + cp.async helpers ----------------
__device__ __forceinline__ uint32_t smem_u32(const void* p) {
    uint32_t a;
    asm("{ .reg .u64 t; cvta.to.shared.u64 t, %1; cvt.u32.u64 %0, t; }"
        : "=r"(a) : "l"(p));
    return a;
}
__device__ __forceinline__ void mma16816(float* d, const uint32_t* a,
                                         const uint32_t* b) {
    asm volatile(
        "mma.sync.aligned.m16n8k16.row.col.f32.bf16.bf16.f32 "
        "{%0,%1,%2,%3}, {%4,%5,%6,%7}, {%8,%9}, {%0,%1,%2,%3};"
        : "+f"(d[0]), "+f"(d[1]), "+f"(d[2]), "+f"(d[3])
        : "r"(a[0]), "r"(a[1]), "r"(a[2]), "r"(a[3]), "r"(b[0]), "r"(b[1]));
}
__device__ __forceinline__ void cp16(uint32_t sdst, const void* gsrc) {
    asm volatile("cp.async.cg.shared.global [%0], [%1], 16;"
                 :: "r"(sdst), "l"(gsrc) : "memory");
}
#define CP_COMMIT() asm volatile("cp.async.commit_group;" ::: "memory")
#define CP_WAIT1() asm volatile("cp.async.wait_group 1;" ::: "memory")
#define CP_WAIT0() asm volatile("cp.async.wait_group 0;" ::: "memory")

// ---------------- split kernels ----------------
__global__ void xsplit_kernel(const float* __restrict__ x,
                              __nv_bfloat16* __restrict__ h,
                              __nv_bfloat16* __restrict__ l, int n) {
    int i = blockIdx.x * blockDim.x + threadIdx.x;
    if (i < n) {
        float v = x[i];
        __nv_bfloat16 hh = __float2bfloat16(v);
        h[i] = hh;
        l[i] = __float2bfloat16(v - __bfloat162float(hh));
    }
}

// w [Kdim, Ndim] fp32 -> th/tl [Ndim, Kdim] bf16 (transposed split)
__global__ void wsplit_kernel(const float* __restrict__ w,
                              __nv_bfloat16* __restrict__ th,
                              __nv_bfloat16* __restrict__ tl,
                              int Kdim, int Ndim) {
    __shared__ float t[32][33];
    int n0 = blockIdx.x * 32, k0 = blockIdx.y * 32;
    int tx = threadIdx.x, ty = threadIdx.y;  // 32 x 8
#pragma unroll
    for (int i = 0; i < 32; i += 8)
        t[ty + i][tx] = w[(size_t)(k0 + ty + i) * Ndim + n0 + tx];
    __syncthreads();
#pragma unroll
    for (int i = 0; i < 32; i += 8) {
        float v = t[tx][ty + i];
        __nv_bfloat16 h = __float2bfloat16(v);
        __nv_bfloat16 l = __float2bfloat16(v - __bfloat162float(h));
        size_t o = (size_t)(n0 + ty + i) * Kdim + k0 + tx;
        th[o] = h;
        tl[o] = l;
    }
}

// ---------------- bf16x3 mma.sync GEMM ----------------
// C[M,N] = sum_k (Ah+Al)[m,k] * (Bh+Bl)[n,k]   (lo*lo dropped)
// A: [M,K] K-major bf16, B: [N,K] K-major bf16 (pre-transposed weights).
// CTA tile 128x128, k-chunk 32, cp.async double buffer.
// Smem per component: [128 rows][40 bf16] (80B row stride, conflict-free frags).
#define COMP_BYTES (128 * 80)          /* 10240 */
#define BUF_BYTES (4 * COMP_BYTES)     /* 40960 */
#define GEMM_SMEM (2 * BUF_BYTES)      /* 81920 */

__device__ __forceinline__ void load_chunk_async(
    const __nv_bfloat16* Ah, const __nv_bfloat16* Al,
    const __nv_bfloat16* Bh, const __nv_bfloat16* Bl,
    int K, int kc, uint32_t sbuf, int tid) {
    const __nv_bfloat16* gp[4] = {Ah, Al, Bh, Bl};
#pragma unroll
    for (int comp = 0; comp < 4; comp++) {
#pragma unroll
        for (int i = 0; i < 2; i++) {
            int id = tid + (i << 8);
            int r = id >> 2, c = id & 3;
            cp16(sbuf + comp * COMP_BYTES + r * 80 + c * 16,
                 gp[comp] + (size_t)r * K + kc + c * 8);
        }
    }
}

__global__ __launch_bounds__(256) void gemm_bf16x3_kernel(
    const __nv_bfloat16* __restrict__ Ah, const __nv_bfloat16* __restrict__ Al,
    const __nv_bfloat16* __restrict__ Bh, const __nv_bfloat16* __restrict__ Bl,
    float* __restrict__ C, int N, int K) {
    extern __shared__ char smem[];
    const uint32_t sb = smem_u32(smem);
    const int tid = threadIdx.x;
    const int wid = tid >> 5, lane = tid & 31;
    const int wm = wid >> 2, wn = wid & 3;  // warp tile: rows wm*64, cols wn*32
    const int bm = blockIdx.y << 7, bn = blockIdx.x << 7;

    const __nv_bfloat16* pAh = Ah + (size_t)bm * K;
    const __nv_bfloat16* pAl = Al + (size_t)bm * K;
    const __nv_bfloat16* pBh = Bh + (size_t)bn * K;
    const __nv_bfloat16* pBl = Bl + (size_t)bn * K;

    float acc[4][4][4];
#pragma unroll
    for (int mt = 0; mt < 4; mt++)
#pragma unroll
        for (int nt = 0; nt < 4; nt++)
#pragma unroll
            for (int i = 0; i < 4; i++) acc[mt][nt][i] = 0.f;

    const int NC = K >> 5;  // 128 chunks of 32

    // prologue: chunk 0 -> buf 0
    load_chunk_async(pAh, pAl, pBh, pBl, K, 0, sb, tid);
    CP_COMMIT();

    const int lr = lane >> 2;       // 0..7
    const int lc4 = (lane & 3) * 4; // byte offset within 16B group

    for (int c = 0; c < NC; c++) {
        const uint32_t buf = sb + (uint32_t)(c & 1) * BUF_BYTES;
        if (c + 1 < NC) {
            load_chunk_async(pAh, pAl, pBh, pBl, K, (c + 1) << 5,
                             sb + (uint32_t)((c + 1) & 1) * BUF_BYTES, tid);
            CP_COMMIT();
            CP_WAIT1();
        } else {
            CP_WAIT0();
        }
        __syncthreads();

        const char* Sah = smem + (buf - sb);
        const char* Sal = Sah + COMP_BYTES;
        const char* Sbh = Sah + 2 * COMP_BYTES;
        const char* Sbl = Sah + 3 * COMP_BYTES;

#pragma unroll
        for (int ks = 0; ks < 2; ks++) {
            const int kb = ks * 32;  // 16 bf16 = 32B
            uint32_t ah[4][4], al[4][4], bh[4][2], bl[4][2];
#pragma unroll
            for (int mt = 0; mt < 4; mt++) {
                int base = (wm * 64 + mt * 16 + lr) * 80 + kb + lc4;
                ah[mt][0] = *(const uint32_t*)(Sah + base);
                ah[mt][1] = *(const uint32_t*)(Sah + base + 640);
                ah[mt][2] = *(const uint32_t*)(Sah + base + 16);
                ah[mt][3] = *(const uint32_t*)(Sah + base + 656);
                al[mt][0] = *(const uint32_t*)(Sal + base);
                al[mt][1] = *(const uint32_t*)(Sal + base + 640);
                al[mt][2] = *(const uint32_t*)(Sal + base + 16);
                al[mt][3] = *(const uint32_t*)(Sal + base + 656);
            }
#pragma unroll
            for (int nt = 0; nt < 4; nt++) {
                int base = (wn * 32 + nt * 8 + lr) * 80 + kb + lc4;
                bh[nt][0] = *(const uint32_t*)(Sbh + base);
                bh[nt][1] = *(const uint32_t*)(Sbh + base + 16);
                bl[nt][0] = *(const uint32_t*)(Sbl + base);
                bl[nt][1] = *(const uint32_t*)(Sbl + base + 16);
            }
#pragma unroll
            for (int mt = 0; mt < 4; mt++)
#pragma unroll
                for (int nt = 0; nt < 4; nt++) {
                    mma16816(acc[mt][nt], ah[mt], bh[nt]);
                    mma16816(acc[mt][nt], ah[mt], bl[nt]);
                    mma16816(acc[mt][nt], al[mt], bh[nt]);
                }
        }
        __syncthreads();
    }

    // epilogue
#pragma unroll
    for (int mt = 0; mt < 4; mt++) {
        int row = bm + wm * 64 + mt * 16 + lr;
#pragma unroll
        for (int nt = 0; nt < 4; nt++) {
            int col = bn + wn * 32 + nt * 8 + (lane & 3) * 2;
            *(float2*)(C + (size_t)row * N + col) =
                make_float2(acc[mt][nt][0], acc[mt][nt][1]);
            *(float2*)(C + (size_t)(row + 8) * N + col) =
                make_float2(acc[mt][nt][2], acc[mt][nt][3]);
        }
    }
}

// ---------------- RoPE (interleaved pairs), in-place on Q and K ----------------
__global__ void rope_kernel(float* __restrict__ Q, float* __restrict__ K,
                            const float* __restrict__ cosv,
                            const float* __restrict__ sinv) {
    const int qn = S * HQ * (HD / 2);
    const int kn = S * HKV * (HD / 2);
    int idx = blockIdx.x * blockDim.x + threadIdx.x;
    if (idx < qn) {
        int i = idx & 63;
        int h = (idx >> 6) & (HQ - 1);
        int s = idx >> 11;
        float c = cosv[(s << 6) + i];
        float sn = sinv[(s << 6) + i];
        float2* p = (float2*)(Q + (size_t)s * D + h * HD) + i;
        float2 v = *p;
        *p = make_float2(v.x * c - v.y * sn, v.x * sn + v.y * c);
    } else if (idx < qn + kn) {
        int t = idx - qn;
        int i = t & 63;
        int h = (t >> 6) & (HKV - 1);
        int s = t >> 9;
        float c = cosv[(s << 6) + i];
        float sn = sinv[(s << 6) + i];
        float2* p = (float2*)(K + (size_t)s * KV_W + h * HD) + i;
        float2 v = *p;
        *p = make_float2(v.x * c - v.y * sn, v.x * sn + v.y * c);
    }
}

// ---------------- Flash attention, fp32, causal, GQA ----------------
#define BQ 64
#define BK 64
#define KT_STRIDE 68
#define PS_STRIDE 65
#define ATTN_SMEM ((BQ * HD + HD * KT_STRIDE + BK * HD + BQ * PS_STRIDE) * 4)

__global__ __launch_bounds__(256) void attn_kernel(
    const float* __restrict__ Qg, const float* __restrict__ Kg,
    const float* __restrict__ Vg, float* __restrict__ Og) {
    extern __shared__ float sm[];
    float* Qs = sm;                   // [64][128]
    float* Kt = Qs + BQ * HD;         // [128][68]  (transposed K)
    float* Vs = Kt + HD * KT_STRIDE;  // [64][128]
    float* Ps = Vs + BK * HD;         // [64][65]

    const int h = blockIdx.y;
    const int q0 = blockIdx.x * BQ;
    const int kvh = h >> 2;  // N_REP = 4
    const int tid = threadIdx.x;
    const int row = tid >> 2;
    const int lr = tid & 3;
    const int tx = tid & 15, ty = tid >> 4;

    for (int i = tid; i < BQ * HD / 4; i += 256) {
        int r = i >> 5, c4 = (i & 31) << 2;
        *(float4*)(Qs + r * HD + c4) =
            *(const float4*)(Qg + (size_t)(q0 + r) * D + h * HD + c4);
    }

    float m_i = -CUDART_INF_F, l_i = 0.f;
    unsigned long long o2[16];
#pragma unroll
    for (int d = 0; d < 16; d++) o2[d] = 0ull;

    const float scale = 0.08838834764831845f;  // 1/sqrt(128)

    for (int k0 = 0; k0 <= q0; k0 += BK) {
        __syncthreads();
        for (int i = tid; i < BK * HD / 4; i += 256) {
            int r = i >> 5, c4 = (i & 31) << 2;
            float4 kv = *(const float4*)(Kg + (size_t)(k0 + r) * KV_W + kvh * HD + c4);
            Kt[(c4 + 0) * KT_STRIDE + r] = kv.x;
            Kt[(c4 + 1) * KT_STRIDE + r] = kv.y;
            Kt[(c4 + 2) * KT_STRIDE + r] = kv.z;
            Kt[(c4 + 3) * KT_STRIDE + r] = kv.w;
            *(float4*)(Vs + r * HD + c4) =
                *(const float4*)(Vg + (size_t)(k0 + r) * KV_W + kvh * HD + c4);
        }
        __syncthreads();

        unsigned long long sc2[4][2];
#pragma unroll
        for (int i = 0; i < 4; i++) { sc2[i][0] = 0ull; sc2[i][1] = 0ull; }
#pragma unroll 4
        for (int kk = 0; kk < HD; kk++) {
            ulonglong2 b = *(ulonglong2*)(Kt + kk * KT_STRIDE + tx * 4);
#pragma unroll
            for (int i = 0; i < 4; i++) {
                float a = Qs[(ty * 4 + i) * HD + kk];
                unsigned long long ad = pack2(a, a);
                ffma2(sc2[i][0], ad, b.x);
                ffma2(sc2[i][1], ad, b.y);
            }
        }
#pragma unroll
        for (int i = 0; i < 4; i++) {
            int qr = q0 + ty * 4 + i;
            float2 p0 = unpack2(sc2[i][0]);
            float2 p1 = unpack2(sc2[i][1]);
            float v[4] = {p0.x, p0.y, p1.x, p1.y};
#pragma unroll
            for (int j = 0; j < 4; j++) {
                int kc = k0 + tx * 4 + j;
                Ps[(ty * 4 + i) * PS_STRIDE + tx * 4 + j] =
                    (kc <= qr) ? v[j] * scale : -CUDART_INF_F;
            }
        }
        __syncwarp();

        float* prow = Ps + row * PS_STRIDE;
        float rmax = -CUDART_INF_F;
#pragma unroll
        for (int j = 0; j < 16; j++) rmax = fmaxf(rmax, prow[lr * 16 + j]);
        rmax = fmaxf(rmax, __shfl_xor_sync(0xffffffff, rmax, 1));
        rmax = fmaxf(rmax, __shfl_xor_sync(0xffffffff, rmax, 2));
        float m_new = fmaxf(m_i, rmax);
        float rsum = 0.f;
#pragma unroll
        for (int j = 0; j < 16; j++) {
            float p = __expf(prow[lr * 16 + j] - m_new);
            prow[lr * 16 + j] = p;
            rsum += p;
        }
        rsum += __shfl_xor_sync(0xffffffff, rsum, 1);
        rsum += __shfl_xor_sync(0xffffffff, rsum, 2);
        float f = __expf(m_i - m_new);
        l_i = l_i * f + rsum;
        m_i = m_new;
        unsigned long long fd = pack2(f, f);
#pragma unroll
        for (int d = 0; d < 16; d++) fmul2(o2[d], fd);
        __syncwarp();

#pragma unroll 2
        for (int j = 0; j < BK; j++) {
            float p = prow[j];
            unsigned long long pd = pack2(p, p);
#pragma unroll
            for (int d = 0; d < 8; d++) {
                ulonglong2 v = *(ulonglong2*)(Vs + j * HD + lr * 4 + d * 16);
                ffma2(o2[2 * d + 0], pd, v.x);
                ffma2(o2[2 * d + 1], pd, v.y);
            }
        }
    }

    float inv = 1.f / l_i;
#pragma unroll
    for (int d = 0; d < 8; d++) {
        float2 p0 = unpack2(o2[2 * d + 0]);
        float2 p1 = unpack2(o2[2 * d + 1]);
        *(float4*)(Og + (size_t)(q0 + row) * D + h * HD + lr * 4 + d * 16) =
            make_float4(p0.x * inv, p0.y * inv, p1.x * inv, p1.y * inv);
    }
}

// ---------------- launch ----------------
extern "C" void kernel_launch(void* const* d_in, const int* in_sizes, int n_in,
                              void* d_out, int out_size) {
    const float* x = (const float*)d_in[0];
    const float* wq = (const float*)d_in[1];
    const float* wk = (const float*)d_in[2];
    const float* wv = (const float*)d_in[3];
    const float* wo = (const float*)d_in[4];
    const float* cosv = (const float*)d_in[5];
    const float* sinv = (const float*)d_in[6];
    float* out = (float*)d_out;

    float *pQ, *pK, *pV, *pA;
    cudaGetSymbolAddress((void**)&pQ, g_Q);
    cudaGetSymbolAddress((void**)&pK, g_K);
    cudaGetSymbolAddress((void**)&pV, g_V);
    cudaGetSymbolAddress((void**)&pA, g_A);
    __nv_bfloat16 *pXh, *pXl, *pWqh, *pWql, *pWkh, *pWkl, *pWvh, *pWvl, *pWoh, *pWol;
    cudaGetSymbolAddress((void**)&pXh, g_Xh);
    cudaGetSymbolAddress((void**)&pXl, g_Xl);
    cudaGetSymbolAddress((void**)&pWqh, g_Wqh);
    cudaGetSymbolAddress((void**)&pWql, g_Wql);
    cudaGetSymbolAddress((void**)&pWkh, g_Wkh);
    cudaGetSymbolAddress((void**)&pWkl, g_Wkl);
    cudaGetSymbolAddress((void**)&pWvh, g_Wvh);
    cudaGetSymbolAddress((void**)&pWvl, g_Wvl);
    cudaGetSymbolAddress((void**)&pWoh, g_Woh);
    cudaGetSymbolAddress((void**)&pWol, g_Wol);

    cudaFuncSetAttribute(attn_kernel, cudaFuncAttributeMaxDynamicSharedMemorySize,
                         ATTN_SMEM);
    cudaFuncSetAttribute(gemm_bf16x3_kernel,
                         cudaFuncAttributeMaxDynamicSharedMemorySize, GEMM_SMEM);

    // hi/lo splits (x) and transposed weight splits
    {
        int n = S * D;
        xsplit_kernel<<<(n + 255) / 256, 256>>>(x, pXh, pXl, n);
    }
    wsplit_kernel<<<dim3(D / 32, D / 32), dim3(32, 8)>>>(wq, pWqh, pWql, D, D);
    wsplit_kernel<<<dim3(KV_W / 32, D / 32), dim3(32, 8)>>>(wk, pWkh, pWkl, D, KV_W);
    wsplit_kernel<<<dim3(KV_W / 32, D / 32), dim3(32, 8)>>>(wv, pWvh, pWvl, D, KV_W);
    wsplit_kernel<<<dim3(D / 32, D / 32), dim3(32, 8)>>>(wo, pWoh, pWol, D, D);

    // QKV projections (mma.sync bf16x3)
    gemm_bf16x3_kernel<<<dim3(D / 128, S / 128), 256, GEMM_SMEM>>>(
        pXh, pXl, pWqh, pWql, pQ, D, D);
    gemm_bf16x3_kernel<<<dim3(KV_W / 128, S / 128), 256, GEMM_SMEM>>>(
        pXh, pXl, pWkh, pWkl, pK, KV_W, D);
    gemm_bf16x3_kernel<<<dim3(KV_W / 128, S / 128), 256, GEMM_SMEM>>>(
        pXh, pXl, pWvh, pWvl, pV, KV_W, D);

    // RoPE on Q and K
    {
        int total = S * HQ * (HD / 2) + S * HKV * (HD / 2);
        rope_kernel<<<(total + 255) / 256, 256>>>(pQ, pK, cosv, sinv);
    }

    // attention (fp32)
    attn_kernel<<<dim3(S / BQ, HQ), 256, ATTN_SMEM>>>(pQ, pK, pV, pA);

    // output projection: split A then bf16x3 GEMM (reuse X buffers)
    {
        int n = S * D;
        xsplit_kernel<<<(n + 255) / 256, 256>>>(pA, pXh, pXl, n);
    }
    gemm_bf16x3_kernel<<<dim3(D / 128, S / 128), 256, GEMM_SMEM>>>(
        pXh, pXl, pWoh, pWol, out, D, D);
}

// round 9
// speedup vs baseline: 2.2341x; 1.6053x over previous
#include <cuda_runtime.h>
#include <cuda_bf16.h>
#include <math_constants.h>
#include <cstdint>
#include <cstddef>

#define S 2048
#define D 4096
#define HQ 32
#define HKV 8
#define HD 128
#define KV_W (HKV * HD) /* 1024 */

// ---------------- scratch (no allocations allowed) ----------------
__device__ float g_Q[(size_t)S * D];     // 32 MB
__device__ float g_K[(size_t)S * KV_W];  // 8 MB
__device__ float g_V[(size_t)S * KV_W];  // 8 MB

// bf16 hi/lo split buffers
__device__ __nv_bfloat16 g_Xh[(size_t)S * D], g_Xl[(size_t)S * D];  // x, then attn out
__device__ __nv_bfloat16 g_Wqh[(size_t)D * D], g_Wql[(size_t)D * D];  // transposed [N,K]
__device__ __nv_bfloat16 g_Wkh[(size_t)KV_W * D], g_Wkl[(size_t)KV_W * D];
__device__ __nv_bfloat16 g_Wvh[(size_t)KV_W * D], g_Wvl[(size_t)KV_W * D];
__device__ __nv_bfloat16 g_Woh[(size_t)D * D], g_Wol[(size_t)D * D];

// ---------------- mma.sync / cp.async / ldmatrix helpers ----------------
__device__ __forceinline__ uint32_t smem_u32(const void* p) {
    uint32_t a;
    asm("{ .reg .u64 t; cvta.to.shared.u64 t, %1; cvt.u32.u64 %0, t; }"
        : "=r"(a) : "l"(p));
    return a;
}
__device__ __forceinline__ void mma16816(float* d, const uint32_t* a,
                                         const uint32_t* b) {
    asm volatile(
        "mma.sync.aligned.m16n8k16.row.col.f32.bf16.bf16.f32 "
        "{%0,%1,%2,%3}, {%4,%5,%6,%7}, {%8,%9}, {%0,%1,%2,%3};"
        : "+f"(d[0]), "+f"(d[1]), "+f"(d[2]), "+f"(d[3])
        : "r"(a[0]), "r"(a[1]), "r"(a[2]), "r"(a[3]), "r"(b[0]), "r"(b[1]));
}
__device__ __forceinline__ void cp16(uint32_t sdst, const void* gsrc) {
    asm volatile("cp.async.cg.shared.global [%0], [%1], 16;"
                 :: "r"(sdst), "l"(gsrc) : "memory");
}
#define CP_COMMIT() asm volatile("cp.async.commit_group;" ::: "memory")
#define CP_WAIT1() asm volatile("cp.async.wait_group 1;" ::: "memory")
#define CP_WAIT0() asm volatile("cp.async.wait_group 0;" ::: "memory")

__device__ __forceinline__ void ldm_x4(uint32_t* r, uint32_t a) {
    asm volatile("ldmatrix.sync.aligned.m8n8.x4.shared.b16 {%0,%1,%2,%3}, [%4];"
                 : "=r"(r[0]), "=r"(r[1]), "=r"(r[2]), "=r"(r[3]) : "r"(a));
}
__device__ __forceinline__ void ldm_x4_t(uint32_t* r, uint32_t a) {
    asm volatile("ldmatrix.sync.aligned.m8n8.x4.trans.shared.b16 {%0,%1,%2,%3}, [%4];"
                 : "=r"(r[0]), "=r"(r[1]), "=r"(r[2]), "=r"(r[3]) : "r"(a));
}

// split two fp32 into packed bf16 hi / lo words (low 16 = first element)
__device__ __forceinline__ void split2(float x, float y, uint32_t& hi, uint32_t& lo) {
    __nv_bfloat16 hx = __float2bfloat16(x), hy = __float2bfloat16(y);
    __nv_bfloat16 lx = __float2bfloat16(x - __bfloat162float(hx));
    __nv_bfloat16 ly = __float2bfloat16(y - __bfloat162float(hy));
    hi = (uint32_t)__bfloat16_as_ushort(hx) | ((uint32_t)__bfloat16_as_ushort(hy) << 16);
    lo = (uint32_t)__bfloat16_as_ushort(lx) | ((uint32_t)__bfloat16_as_ushort(ly) << 16);
}

// ---------------- split kernels ----------------
__global__ void xsplit_kernel(const float* __restrict__ x,
                              __nv_bfloat16* __restrict__ h,
                              __nv_bfloat16* __restrict__ l, int n) {
    int i = blockIdx.x * blockDim.x + threadIdx.x;
    if (i < n) {
        float v = x[i];
        __nv_bfloat16 hh = __float2bfloat16(v);
        h[i] = hh;
        l[i] = __float2bfloat16(v - __bfloat162float(hh));
    }
}

// w [Kdim, Ndim] fp32 -> th/tl [Ndim, Kdim] bf16 (transposed split)
__global__ void wsplit_kernel(const float* __restrict__ w,
                              __nv_bfloat16* __restrict__ th,
                              __nv_bfloat16* __restrict__ tl,
                              int Kdim, int Ndim) {
    __shared__ float t[32][33];
    int n0 = blockIdx.x * 32, k0 = blockIdx.y * 32;
    int tx = threadIdx.x, ty = threadIdx.y;  // 32 x 8
#pragma unroll
    for (int i = 0; i < 32; i += 8)
        t[ty + i][tx] = w[(size_t)(k0 + ty + i) * Ndim + n0 + tx];
    __syncthreads();
#pragma unroll
    for (int i = 0; i < 32; i += 8) {
        float v = t[tx][ty + i];
        __nv_bfloat16 h = __float2bfloat16(v);
        __nv_bfloat16 l = __float2bfloat16(v - __bfloat162float(h));
        size_t o = (size_t)(n0 + ty + i) * Kdim + k0 + tx;
        th[o] = h;
        tl[o] = l;
    }
}

// ---------------- bf16x3 mma.sync GEMM (R7-passing version) ----------------
#define COMP_BYTES (128 * 80)
#define BUF_BYTES (4 * COMP_BYTES)
#define GEMM_SMEM (2 * BUF_BYTES)

__device__ __forceinline__ void load_chunk_async(
    const __nv_bfloat16* Ah, const __nv_bfloat16* Al,
    const __nv_bfloat16* Bh, const __nv_bfloat16* Bl,
    int K, int kc, uint32_t sbuf, int tid) {
    const __nv_bfloat16* gp[4] = {Ah, Al, Bh, Bl};
#pragma unroll
    for (int comp = 0; comp < 4; comp++) {
#pragma unroll
        for (int i = 0; i < 2; i++) {
            int id = tid + (i << 8);
            int r = id >> 2, c = id & 3;
            cp16(sbuf + comp * COMP_BYTES + r * 80 + c * 16,
                 gp[comp] + (size_t)r * K + kc + c * 8);
        }
    }
}

__global__ __launch_bounds__(256) void gemm_bf16x3_kernel(
    const __nv_bfloat16* __restrict__ Ah, const __nv_bfloat16* __restrict__ Al,
    const __nv_bfloat16* __restrict__ Bh, const __nv_bfloat16* __restrict__ Bl,
    float* __restrict__ C, int N, int K) {
    extern __shared__ char smem[];
    const uint32_t sb = smem_u32(smem);
    const int tid = threadIdx.x;
    const int wid = tid >> 5, lane = tid & 31;
    const int wm = wid >> 2, wn = wid & 3;
    const int bm = blockIdx.y << 7, bn = blockIdx.x << 7;

    const __nv_bfloat16* pAh = Ah + (size_t)bm * K;
    const __nv_bfloat16* pAl = Al + (size_t)bm * K;
    const __nv_bfloat16* pBh = Bh + (size_t)bn * K;
    const __nv_bfloat16* pBl = Bl + (size_t)bn * K;

    float acc[4][4][4];
#pragma unroll
    for (int mt = 0; mt < 4; mt++)
#pragma unroll
        for (int nt = 0; nt < 4; nt++)
#pragma unroll
            for (int i = 0; i < 4; i++) acc[mt][nt][i] = 0.f;

    const int NC = K >> 5;
    load_chunk_async(pAh, pAl, pBh, pBl, K, 0, sb, tid);
    CP_COMMIT();

    const int lr = lane >> 2;
    const int lc4 = (lane & 3) * 4;

    for (int c = 0; c < NC; c++) {
        const uint32_t buf = sb + (uint32_t)(c & 1) * BUF_BYTES;
        if (c + 1 < NC) {
            load_chunk_async(pAh, pAl, pBh, pBl, K, (c + 1) << 5,
                             sb + (uint32_t)((c + 1) & 1) * BUF_BYTES, tid);
            CP_COMMIT();
            CP_WAIT1();
        } else {
            CP_WAIT0();
        }
        __syncthreads();

        const char* Sah = smem + (buf - sb);
        const char* Sal = Sah + COMP_BYTES;
        const char* Sbh = Sah + 2 * COMP_BYTES;
        const char* Sbl = Sah + 3 * COMP_BYTES;

#pragma unroll
        for (int ks = 0; ks < 2; ks++) {
            const int kb = ks * 32;
            uint32_t ah[4][4], al[4][4], bh[4][2], bl[4][2];
#pragma unroll
            for (int mt = 0; mt < 4; mt++) {
                int base = (wm * 64 + mt * 16 + lr) * 80 + kb + lc4;
                ah[mt][0] = *(const uint32_t*)(Sah + base);
                ah[mt][1] = *(const uint32_t*)(Sah + base + 640);
                ah[mt][2] = *(const uint32_t*)(Sah + base + 16);
                ah[mt][3] = *(const uint32_t*)(Sah + base + 656);
                al[mt][0] = *(const uint32_t*)(Sal + base);
                al[mt][1] = *(const uint32_t*)(Sal + base + 640);
                al[mt][2] = *(const uint32_t*)(Sal + base + 16);
                al[mt][3] = *(const uint32_t*)(Sal + base + 656);
            }
#pragma unroll
            for (int nt = 0; nt < 4; nt++) {
                int base = (wn * 32 + nt * 8 + lr) * 80 + kb + lc4;
                bh[nt][0] = *(const uint32_t*)(Sbh + base);
                bh[nt][1] = *(const uint32_t*)(Sbh + base + 16);
                bl[nt][0] = *(const uint32_t*)(Sbl + base);
                bl[nt][1] = *(const uint32_t*)(Sbl + base + 16);
            }
#pragma unroll
            for (int mt = 0; mt < 4; mt++)
#pragma unroll
                for (int nt = 0; nt < 4; nt++) {
                    mma16816(acc[mt][nt], ah[mt], bh[nt]);
                    mma16816(acc[mt][nt], ah[mt], bl[nt]);
                    mma16816(acc[mt][nt], al[mt], bh[nt]);
                }
        }
        __syncthreads();
    }

#pragma unroll
    for (int mt = 0; mt < 4; mt++) {
        int row = bm + wm * 64 + mt * 16 + lr;
#pragma unroll
        for (int nt = 0; nt < 4; nt++) {
            int col = bn + wn * 32 + nt * 8 + (lane & 3) * 2;
            *(float2*)(C + (size_t)row * N + col) =
                make_float2(acc[mt][nt][0], acc[mt][nt][1]);
            *(float2*)(C + (size_t)(row + 8) * N + col) =
                make_float2(acc[mt][nt][2], acc[mt][nt][3]);
        }
    }
}

// ---------------- RoPE (interleaved pairs), in-place on Q and K ----------------
__global__ void rope_kernel(float* __restrict__ Q, float* __restrict__ K,
                            const float* __restrict__ cosv,
                            const float* __restrict__ sinv) {
    const int qn = S * HQ * (HD / 2);
    const int kn = S * HKV * (HD / 2);
    int idx = blockIdx.x * blockDim.x + threadIdx.x;
    if (idx < qn) {
        int i = idx & 63;
        int h = (idx >> 6) & (HQ - 1);
        int s = idx >> 11;
        float c = cosv[(s << 6) + i];
        float sn = sinv[(s << 6) + i];
        float2* p = (float2*)(Q + (size_t)s * D + h * HD) + i;
        float2 v = *p;
        *p = make_float2(v.x * c - v.y * sn, v.x * sn + v.y * c);
    } else if (idx < qn + kn) {
        int t = idx - qn;
        int i = t & 63;
        int h = (t >> 6) & (HKV - 1);
        int s = t >> 9;
        float c = cosv[(s << 6) + i];
        float sn = sinv[(s << 6) + i];
        float2* p = (float2*)(K + (size_t)s * KV_W + h * HD) + i;
        float2 v = *p;
        *p = make_float2(v.x * c - v.y * sn, v.x * sn + v.y * c);
    }
}

// ---------------- Flash attention, mma.sync bf16 (compensated scores) ----------
// BQ=BK=64. 8 warps: scores warp = 16 rows x 32 cols (wm=wid&3, wn=wid>>2);
// PV warp = 16 rows x 64 cols. Output written as bf16 hi/lo (feeds wo GEMM).
#define QK_STR 272 /* bytes per 128-col bf16 row */
#define P_STR 144  /* bytes per 64-col bf16 row */
#define PS_STR 68  /* floats per score row */
#define OFF_QH 0
#define OFF_QL 17408
#define OFF_KH 34816
#define OFF_KL 52224
#define OFF_VH 69632
#define OFF_VL 87040
#define OFF_PS 104448
#define OFF_PB 121856
#define OFF_FR 131072
#define OFF_IL 131328
#define ATTN2_SMEM 131584

__global__ __launch_bounds__(256) void attn_mma_kernel(
    const float* __restrict__ Qg, const float* __restrict__ Kg,
    const float* __restrict__ Vg,
    __nv_bfloat16* __restrict__ Oh, __nv_bfloat16* __restrict__ Ol) {
    extern __shared__ char smb[];
    const uint32_t sb = smem_u32(smb);
    const int tid = threadIdx.x, wid = tid >> 5, lane = tid & 31;
    const int h = blockIdx.y, q0 = blockIdx.x * 64, kvh = h >> 2;
    const int wm = wid & 3, wn = wid >> 2;
    const int g8 = lane >> 3, l8 = lane & 7;
    const int row = tid >> 2, lr = tid & 3;  // softmax role
    const int r0 = wm * 16 + (lane >> 2);    // c-frag row (r1 = r0+8)
    const float scale = 0.08838834764831845f;  // 1/sqrt(128)

    float* fRp = (float*)(smb + OFF_FR);
    float* iLp = (float*)(smb + OFF_IL);

    // load Q tile, pre-scale, hi/lo split
    for (int i = tid; i < 2048; i += 256) {
        int r = i >> 5, c4 = (i & 31) << 2;
        float4 q = *(const float4*)(Qg + (size_t)(q0 + r) * D + h * HD + c4);
        uint32_t h0, l0, h1, l1;
        split2(q.x * scale, q.y * scale, h0, l0);
        split2(q.z * scale, q.w * scale, h1, l1);
        *(uint2*)(smb + OFF_QH + r * QK_STR + c4 * 2) = make_uint2(h0, h1);
        *(uint2*)(smb + OFF_QL + r * QK_STR + c4 * 2) = make_uint2(l0, l1);
    }

    float m_i = -CUDART_INF_F, l_i = 0.f;
    float oacc[8][4];
#pragma unroll
    for (int nt = 0; nt < 8; nt++)
#pragma unroll
        for (int i = 0; i < 4; i++) oacc[nt][i] = 0.f;

    // ldmatrix base offsets
    const uint32_t aRow = (uint32_t)(wm * 16 + (g8 & 1) * 8 + l8);
    const uint32_t qhB = sb + OFF_QH + aRow * QK_STR;
    const uint32_t qlB = sb + OFF_QL + aRow * QK_STR;
    const uint32_t pB = sb + OFF_PB + aRow * P_STR;
    const uint32_t aColOfs = (uint32_t)((g8 >> 1) * 8) * 2;

    for (int k0 = 0; k0 <= q0; k0 += 64) {
        __syncthreads();  // prior iteration consumers done
        // load K and V tiles, hi/lo split (V transposed later by ldmatrix.trans)
        for (int i = tid; i < 2048; i += 256) {
            int r = i >> 5, c4 = (i & 31) << 2;
            float4 kv = *(const float4*)(Kg + (size_t)(k0 + r) * KV_W + kvh * HD + c4);
            float4 vv = *(const float4*)(Vg + (size_t)(k0 + r) * KV_W + kvh * HD + c4);
            uint32_t h0, l0, h1, l1;
            split2(kv.x, kv.y, h0, l0);
            split2(kv.z, kv.w, h1, l1);
            *(uint2*)(smb + OFF_KH + r * QK_STR + c4 * 2) = make_uint2(h0, h1);
            *(uint2*)(smb + OFF_KL + r * QK_STR + c4 * 2) = make_uint2(l0, l1);
            split2(vv.x, vv.y, h0, l0);
            split2(vv.z, vv.w, h1, l1);
            *(uint2*)(smb + OFF_VH + r * QK_STR + c4 * 2) = make_uint2(h0, h1);
            *(uint2*)(smb + OFF_VL + r * QK_STR + c4 * 2) = make_uint2(l0, l1);
        }
        __syncthreads();

        // ---- scores: S = Q K^T (Qh*Kh + Qh*Kl + Ql*Kh), pre-scaled ----
        float sacc[4][4];
#pragma unroll
        for (int nt = 0; nt < 4; nt++)
#pragma unroll
            for (int i = 0; i < 4; i++) sacc[nt][i] = 0.f;

#pragma unroll
        for (int ks = 0; ks < 8; ks++) {
            uint32_t aH[4], aL[4];
            uint32_t co = (uint32_t)(ks * 16) * 2 + aColOfs;
            ldm_x4(aH, qhB + co);
            ldm_x4(aL, qlB + co);
#pragma unroll
            for (int ntp = 0; ntp < 2; ntp++) {
                uint32_t bH[4], bL[4];
                uint32_t nrow = (uint32_t)(wn * 32 + ntp * 16 + (g8 >> 1) * 8 + l8);
                uint32_t kof = (uint32_t)(ks * 16 + (g8 & 1) * 8) * 2;
                ldm_x4(bH, sb + OFF_KH + nrow * QK_STR + kof);
                ldm_x4(bL, sb + OFF_KL + nrow * QK_STR + kof);
                mma16816(sacc[2 * ntp], aH, bH);
                mma16816(sacc[2 * ntp], aH, bL);
                mma16816(sacc[2 * ntp], aL, bH);
                mma16816(sacc[2 * ntp + 1], aH, bH + 2);
                mma16816(sacc[2 * ntp + 1], aH, bL + 2);
                mma16816(sacc[2 * ntp + 1], aL, bH + 2);
            }
        }
        // write masked scores to Ps
        {
            float* Ps = (float*)(smb + OFF_PS);
            int qr0 = q0 + r0, qr1 = qr0 + 8;
#pragma unroll
            for (int nt = 0; nt < 4; nt++) {
                int c = wn * 32 + nt * 8 + (lane & 3) * 2;
                int kc = k0 + c;
                Ps[r0 * PS_STR + c] = (kc <= qr0) ? sacc[nt][0] : -CUDART_INF_F;
                Ps[r0 * PS_STR + c + 1] = (kc + 1 <= qr0) ? sacc[nt][1] : -CUDART_INF_F;
                Ps[(r0 + 8) * PS_STR + c] = (kc <= qr1) ? sacc[nt][2] : -CUDART_INF_F;
                Ps[(r0 + 8) * PS_STR + c + 1] =
                    (kc + 1 <= qr1) ? sacc[nt][3] : -CUDART_INF_F;
            }
        }
        __syncthreads();

        // ---- online softmax (thread role: row, lr owns 16 cols) ----
        {
            const float* prow = (const float*)(smb + OFF_PS) + row * PS_STR + lr * 16;
            float pv[16];
            float rmax = -CUDART_INF_F;
#pragma unroll
            for (int j = 0; j < 16; j++) {
                pv[j] = prow[j];
                rmax = fmaxf(rmax, pv[j]);
            }
            rmax = fmaxf(rmax, __shfl_xor_sync(0xffffffff, rmax, 1));
            rmax = fmaxf(rmax, __shfl_xor_sync(0xffffffff, rmax, 2));
            float m_new = fmaxf(m_i, rmax);
            float rsum = 0.f;
#pragma unroll
            for (int j = 0; j < 16; j++) {
                pv[j] = __expf(pv[j] - m_new);
                rsum += pv[j];
            }
            rsum += __shfl_xor_sync(0xffffffff, rsum, 1);
            rsum += __shfl_xor_sync(0xffffffff, rsum, 2);
            float f = __expf(m_i - m_new);
            l_i = l_i * f + rsum;
            m_i = m_new;
            if (lr == 0) fRp[row] = f;
            // write P bf16
#pragma unroll
            for (int j = 0; j < 8; j++) {
                uint32_t w = (uint32_t)__bfloat16_as_ushort(__float2bfloat16(pv[2 * j])) |
                             ((uint32_t)__bfloat16_as_ushort(__float2bfloat16(pv[2 * j + 1]))
                              << 16);
                *(uint32_t*)(smb + OFF_PB + row * P_STR + (lr * 16 + 2 * j) * 2) = w;
            }
        }
        __syncthreads();

        // ---- PV: O = P * V (Vh + Vl), online rescale ----
        {
            float f0 = fRp[r0], f1 = fRp[r0 + 8];
#pragma unroll
            for (int nt = 0; nt < 8; nt++) {
                oacc[nt][0] *= f0;
                oacc[nt][1] *= f0;
                oacc[nt][2] *= f1;
                oacc[nt][3] *= f1;
            }
#pragma unroll
            for (int ks = 0; ks < 4; ks++) {
                uint32_t aP[4];
                ldm_x4(aP, pB + (uint32_t)(ks * 16) * 2 + ((uint32_t)((g8 >> 1) * 8) * 2));
                uint32_t krow = (uint32_t)(ks * 16 + (g8 & 1) * 8 + l8);
#pragma unroll
                for (int ntp = 0; ntp < 4; ntp++) {
                    uint32_t bH[4], bL[4];
                    uint32_t ncol = (uint32_t)(wn * 64 + ntp * 16 + (g8 >> 1) * 8);
                    ldm_x4_t(bH, sb + OFF_VH + krow * QK_STR + ncol * 2);
                    ldm_x4_t(bL, sb + OFF_VL + krow * QK_STR + ncol * 2);
                    mma16816(oacc[2 * ntp], aP, bH);
                    mma16816(oacc[2 * ntp], aP, bL);
                    mma16816(oacc[2 * ntp + 1], aP, bH + 2);
                    mma16816(oacc[2 * ntp + 1], aP, bL + 2);
                }
            }
        }
    }

    if (lr == 0) iLp[row] = 1.f / l_i;
    __syncthreads();

    // finalize: scale by 1/l, write bf16 hi/lo directly (feeds wo GEMM)
    {
        float i0 = iLp[r0], i1 = iLp[r0 + 8];
#pragma unroll
        for (int nt = 0; nt < 8; nt++) {
            int col = h * HD + wn * 64 + nt * 8 + (lane & 3) * 2;
            size_t o0 = (size_t)(q0 + r0) * D + col;
            size_t o1 = (size_t)(q0 + r0 + 8) * D + col;
            uint32_t hh, ll;
            split2(oacc[nt][0] * i0, oacc[nt][1] * i0, hh, ll);
            *(uint32_t*)(Oh + o0) = hh;
            *(uint32_t*)(Ol + o0) = ll;
            split2(oacc[nt][2] * i1, oacc[nt][3] * i1, hh, ll);
            *(uint32_t*)(Oh + o1) = hh;
            *(uint32_t*)(Ol + o1) = ll;
        }
    }
}

// ---------------- launch ----------------
extern "C" void kernel_launch(void* const* d_in, const int* in_sizes, int n_in,
                              void* d_out, int out_size) {
    const float* x = (const float*)d_in[0];
    const float* wq = (const float*)d_in[1];
    const float* wk = (const float*)d_in[2];
    const float* wv = (const float*)d_in[3];
    const float* wo = (const float*)d_in[4];
    const float* cosv = (const float*)d_in[5];
    const float* sinv = (const float*)d_in[6];
    float* out = (float*)d_out;

    float *pQ, *pK, *pV;
    cudaGetSymbolAddress((void**)&pQ, g_Q);
    cudaGetSymbolAddress((void**)&pK, g_K);
    cudaGetSymbolAddress((void**)&pV, g_V);
    __nv_bfloat16 *pXh, *pXl, *pWqh, *pWql, *pWkh, *pWkl, *pWvh, *pWvl, *pWoh, *pWol;
    cudaGetSymbolAddress((void**)&pXh, g_Xh);
    cudaGetSymbolAddress((void**)&pXl, g_Xl);
    cudaGetSymbolAddress((void**)&pWqh, g_Wqh);
    cudaGetSymbolAddress((void**)&pWql, g_Wql);
    cudaGetSymbolAddress((void**)&pWkh, g_Wkh);
    cudaGetSymbolAddress((void**)&pWkl, g_Wkl);
    cudaGetSymbolAddress((void**)&pWvh, g_Wvh);
    cudaGetSymbolAddress((void**)&pWvl, g_Wvl);
    cudaGetSymbolAddress((void**)&pWoh, g_Woh);
    cudaGetSymbolAddress((void**)&pWol, g_Wol);

    cudaFuncSetAttribute(gemm_bf16x3_kernel,
                         cudaFuncAttributeMaxDynamicSharedMemorySize, GEMM_SMEM);
    cudaFuncSetAttribute(attn_mma_kernel,
                         cudaFuncAttributeMaxDynamicSharedMemorySize, ATTN2_SMEM);

    // x split + transposed weight splits
    {
        int n = S * D;
        xsplit_kernel<<<(n + 255) / 256, 256>>>(x, pXh, pXl, n);
    }
    wsplit_kernel<<<dim3(D / 32, D / 32), dim3(32, 8)>>>(wq, pWqh, pWql, D, D);
    wsplit_kernel<<<dim3(KV_W / 32, D / 32), dim3(32, 8)>>>(wk, pWkh, pWkl, D, KV_W);
    wsplit_kernel<<<dim3(KV_W / 32, D / 32), dim3(32, 8)>>>(wv, pWvh, pWvl, D, KV_W);
    wsplit_kernel<<<dim3(D / 32, D / 32), dim3(32, 8)>>>(wo, pWoh, pWol, D, D);

    // QKV projections (mma.sync bf16x3)
    gemm_bf16x3_kernel<<<dim3(D / 128, S / 128), 256, GEMM_SMEM>>>(
        pXh, pXl, pWqh, pWql, pQ, D, D);
    gemm_bf16x3_kernel<<<dim3(KV_W / 128, S / 128), 256, GEMM_SMEM>>>(
        pXh, pXl, pWkh, pWkl, pK, KV_W, D);
    gemm_bf16x3_kernel<<<dim3(KV_W / 128, S / 128), 256, GEMM_SMEM>>>(
        pXh, pXl, pWvh, pWvl, pV, KV_W, D);

    // RoPE on Q and K (fp32)
    {
        int total = S * HQ * (HD / 2) + S * HKV * (HD / 2);
        rope_kernel<<<(total + 255) / 256, 256>>>(pQ, pK, cosv, sinv);
    }

    // attention (mma.sync, writes bf16 hi/lo directly into X buffers)
    attn_mma_kernel<<<dim3(S / 64, HQ), 256, ATTN2_SMEM>>>(pQ, pK, pV, pXh, pXl);

    // output projection
    gemm_bf16x3_kernel<<<dim3(D / 128, S / 128), 256, GEMM_SMEM>>>(
        pXh, pXl, pWoh, pWol, out, D, D);
}

// round 10
// speedup vs baseline: 2.2371x; 1.0013x over previous
#include <cuda_runtime.h>
#include <cuda_bf16.h>
#include <cuda_fp16.h>
#include <math_constants.h>
#include <cstdint>
#include <cstddef>

#define S 2048
#define D 4096
#define HQ 32
#define HKV 8
#define HD 128
#define KV_W (HKV * HD) /* 1024 */

// ---------------- scratch (no allocations allowed) ----------------
__device__ float g_Q[(size_t)S * D];     // 32 MB
__device__ float g_K[(size_t)S * KV_W];  // 8 MB
__device__ float g_V[(size_t)S * KV_W];  // 8 MB

// bf16 hi/lo split buffers
__device__ __nv_bfloat16 g_Xh[(size_t)S * D], g_Xl[(size_t)S * D];  // x, then attn out
__device__ __nv_bfloat16 g_Wqh[(size_t)D * D], g_Wql[(size_t)D * D];  // transposed [N,K]
__device__ __nv_bfloat16 g_Wkh[(size_t)KV_W * D], g_Wkl[(size_t)KV_W * D];
__device__ __nv_bfloat16 g_Wvh[(size_t)KV_W * D], g_Wvl[(size_t)KV_W * D];
__device__ __nv_bfloat16 g_Woh[(size_t)D * D], g_Wol[(size_t)D * D];

// ---------------- mma.sync / cp.async / ldmatrix helpers ----------------
__device__ __forceinline__ uint32_t smem_u32(const void* p) {
    uint32_t a;
    asm("{ .reg .u64 t; cvta.to.shared.u64 t, %1; cvt.u32.u64 %0, t; }"
        : "=r"(a) : "l"(p));
    return a;
}
// bf16 mma (GEMMs)
__device__ __forceinline__ void mma16816(float* d, const uint32_t* a,
                                         const uint32_t* b) {
    asm volatile(
        "mma.sync.aligned.m16n8k16.row.col.f32.bf16.bf16.f32 "
        "{%0,%1,%2,%3}, {%4,%5,%6,%7}, {%8,%9}, {%0,%1,%2,%3};"
        : "+f"(d[0]), "+f"(d[1]), "+f"(d[2]), "+f"(d[3])
        : "r"(a[0]), "r"(a[1]), "r"(a[2]), "r"(a[3]), "r"(b[0]), "r"(b[1]));
}
// fp16 mma (attention)
__device__ __forceinline__ void mma16816h(float* d, const uint32_t* a,
                                          const uint32_t* b) {
    asm volatile(
        "mma.sync.aligned.m16n8k16.row.col.f32.f16.f16.f32 "
        "{%0,%1,%2,%3}, {%4,%5,%6,%7}, {%8,%9}, {%0,%1,%2,%3};"
        : "+f"(d[0]), "+f"(d[1]), "+f"(d[2]), "+f"(d[3])
        : "r"(a[0]), "r"(a[1]), "r"(a[2]), "r"(a[3]), "r"(b[0]), "r"(b[1]));
}
__device__ __forceinline__ void cp16(uint32_t sdst, const void* gsrc) {
    asm volatile("cp.async.cg.shared.global [%0], [%1], 16;"
                 :: "r"(sdst), "l"(gsrc) : "memory");
}
#define CP_COMMIT() asm volatile("cp.async.commit_group;" ::: "memory")
#define CP_WAIT1() asm volatile("cp.async.wait_group 1;" ::: "memory")
#define CP_WAIT0() asm volatile("cp.async.wait_group 0;" ::: "memory")

__device__ __forceinline__ void ldm_x4(uint32_t* r, uint32_t a) {
    asm volatile("ldmatrix.sync.aligned.m8n8.x4.shared.b16 {%0,%1,%2,%3}, [%4];"
                 : "=r"(r[0]), "=r"(r[1]), "=r"(r[2]), "=r"(r[3]) : "r"(a));
}
__device__ __forceinline__ void ldm_x4_t(uint32_t* r, uint32_t a) {
    asm volatile("ldmatrix.sync.aligned.m8n8.x4.trans.shared.b16 {%0,%1,%2,%3}, [%4];"
                 : "=r"(r[0]), "=r"(r[1]), "=r"(r[2]), "=r"(r[3]) : "r"(a));
}

// split two fp32 into packed bf16 hi / lo words (low 16 = first element)
__device__ __forceinline__ void split2(float x, float y, uint32_t& hi, uint32_t& lo) {
    __nv_bfloat16 hx = __float2bfloat16(x), hy = __float2bfloat16(y);
    __nv_bfloat16 lx = __float2bfloat16(x - __bfloat162float(hx));
    __nv_bfloat16 ly = __float2bfloat16(y - __bfloat162float(hy));
    hi = (uint32_t)__bfloat16_as_ushort(hx) | ((uint32_t)__bfloat16_as_ushort(hy) << 16);
    lo = (uint32_t)__bfloat16_as_ushort(lx) | ((uint32_t)__bfloat16_as_ushort(ly) << 16);
}
// split two fp32 into packed fp16 hi / lo words
__device__ __forceinline__ void split2h(float x, float y, uint32_t& hi, uint32_t& lo) {
    __half hx = __float2half_rn(x), hy = __float2half_rn(y);
    __half lx = __float2half_rn(x - __half2float(hx));
    __half ly = __float2half_rn(y - __half2float(hy));
    hi = (uint32_t)__half_as_ushort(hx) | ((uint32_t)__half_as_ushort(hy) << 16);
    lo = (uint32_t)__half_as_ushort(lx) | ((uint32_t)__half_as_ushort(ly) << 16);
}

// ---------------- split kernels ----------------
__global__ void xsplit_kernel(const float* __restrict__ x,
                              __nv_bfloat16* __restrict__ h,
                              __nv_bfloat16* __restrict__ l, int n) {
    int i = blockIdx.x * blockDim.x + threadIdx.x;
    if (i < n) {
        float v = x[i];
        __nv_bfloat16 hh = __float2bfloat16(v);
        h[i] = hh;
        l[i] = __float2bfloat16(v - __bfloat162float(hh));
    }
}

// w [Kdim, Ndim] fp32 -> th/tl [Ndim, Kdim] bf16 (transposed split)
__global__ void wsplit_kernel(const float* __restrict__ w,
                              __nv_bfloat16* __restrict__ th,
                              __nv_bfloat16* __restrict__ tl,
                              int Kdim, int Ndim) {
    __shared__ float t[32][33];
    int n0 = blockIdx.x * 32, k0 = blockIdx.y * 32;
    int tx = threadIdx.x, ty = threadIdx.y;  // 32 x 8
#pragma unroll
    for (int i = 0; i < 32; i += 8)
        t[ty + i][tx] = w[(size_t)(k0 + ty + i) * Ndim + n0 + tx];
    __syncthreads();
#pragma unroll
    for (int i = 0; i < 32; i += 8) {
        float v = t[tx][ty + i];
        __nv_bfloat16 h = __float2bfloat16(v);
        __nv_bfloat16 l = __float2bfloat16(v - __bfloat162float(h));
        size_t o = (size_t)(n0 + ty + i) * Kdim + k0 + tx;
        th[o] = h;
        tl[o] = l;
    }
}

// ---------------- bf16x3 mma.sync GEMM (ldmatrix fragments) ----------------
#define COMP_BYTES (128 * 80)
#define BUF_BYTES (4 * COMP_BYTES)
#define GEMM_SMEM (2 * BUF_BYTES)

__device__ __forceinline__ void load_chunk_async(
    const __nv_bfloat16* Ah, const __nv_bfloat16* Al,
    const __nv_bfloat16* Bh, const __nv_bfloat16* Bl,
    int K, int kc, uint32_t sbuf, int tid) {
    const __nv_bfloat16* gp[4] = {Ah, Al, Bh, Bl};
#pragma unroll
    for (int comp = 0; comp < 4; comp++) {
#pragma unroll
        for (int i = 0; i < 2; i++) {
            int id = tid + (i << 8);
            int r = id >> 2, c = id & 3;
            cp16(sbuf + comp * COMP_BYTES + r * 80 + c * 16,
                 gp[comp] + (size_t)r * K + kc + c * 8);
        }
    }
}

__global__ __launch_bounds__(256) void gemm_bf16x3_kernel(
    const __nv_bfloat16* __restrict__ Ah, const __nv_bfloat16* __restrict__ Al,
    const __nv_bfloat16* __restrict__ Bh, const __nv_bfloat16* __restrict__ Bl,
    float* __restrict__ C, int N, int K) {
    extern __shared__ char smem[];
    const uint32_t sb = smem_u32(smem);
    const int tid = threadIdx.x;
    const int wid = tid >> 5, lane = tid & 31;
    const int wm = wid >> 2, wn = wid & 3;
    const int g8 = lane >> 3, l8 = lane & 7;
    const int bm = blockIdx.y << 7, bn = blockIdx.x << 7;

    const __nv_bfloat16* pAh = Ah + (size_t)bm * K;
    const __nv_bfloat16* pAl = Al + (size_t)bm * K;
    const __nv_bfloat16* pBh = Bh + (size_t)bn * K;
    const __nv_bfloat16* pBl = Bl + (size_t)bn * K;

    float acc[4][4][4];
#pragma unroll
    for (int mt = 0; mt < 4; mt++)
#pragma unroll
        for (int nt = 0; nt < 4; nt++)
#pragma unroll
            for (int i = 0; i < 4; i++) acc[mt][nt][i] = 0.f;

    const int NC = K >> 5;
    load_chunk_async(pAh, pAl, pBh, pBl, K, 0, sb, tid);
    CP_COMMIT();

    // ldmatrix address bases (within a component)
    const uint32_t aOff = (uint32_t)((wm * 64 + (g8 & 1) * 8 + l8) * 80 + (g8 >> 1) * 16);
    const uint32_t bOff = (uint32_t)((wn * 32 + (g8 >> 1) * 8 + l8) * 80 + (g8 & 1) * 16);

    for (int c = 0; c < NC; c++) {
        const uint32_t buf = sb + (uint32_t)(c & 1) * BUF_BYTES;
        if (c + 1 < NC) {
            load_chunk_async(pAh, pAl, pBh, pBl, K, (c + 1) << 5,
                             sb + (uint32_t)((c + 1) & 1) * BUF_BYTES, tid);
            CP_COMMIT();
            CP_WAIT1();
        } else {
            CP_WAIT0();
        }
        __syncthreads();

#pragma unroll
        for (int ks = 0; ks < 2; ks++) {
            const uint32_t kb = (uint32_t)(ks * 32);
            uint32_t ah[4][4], al[4][4], bh[2][4], bl[2][4];
#pragma unroll
            for (int mt = 0; mt < 4; mt++) {
                uint32_t ao = buf + aOff + (uint32_t)(mt * 16 * 80) + kb;
                ldm_x4(ah[mt], ao);
                ldm_x4(al[mt], ao + COMP_BYTES);
            }
#pragma unroll
            for (int ntp = 0; ntp < 2; ntp++) {
                uint32_t bo = buf + bOff + (uint32_t)(ntp * 16 * 80) + kb;
                ldm_x4(bh[ntp], bo + 2 * COMP_BYTES);
                ldm_x4(bl[ntp], bo + 3 * COMP_BYTES);
            }
#pragma unroll
            for (int mt = 0; mt < 4; mt++)
#pragma unroll
                for (int ntp = 0; ntp < 2; ntp++) {
                    mma16816(acc[mt][2 * ntp], ah[mt], bh[ntp]);
                    mma16816(acc[mt][2 * ntp], ah[mt], bl[ntp]);
                    mma16816(acc[mt][2 * ntp], al[mt], bh[ntp]);
                    mma16816(acc[mt][2 * ntp + 1], ah[mt], bh[ntp] + 2);
                    mma16816(acc[mt][2 * ntp + 1], ah[mt], bl[ntp] + 2);
                    mma16816(acc[mt][2 * ntp + 1], al[mt], bh[ntp] + 2);
                }
        }
        __syncthreads();
    }

#pragma unroll
    for (int mt = 0; mt < 4; mt++) {
        int row = bm + wm * 64 + mt * 16 + (lane >> 2);
#pragma unroll
        for (int nt = 0; nt < 4; nt++) {
            int col = bn + wn * 32 + nt * 8 + (lane & 3) * 2;
            *(float2*)(C + (size_t)row * N + col) =
                make_float2(acc[mt][nt][0], acc[mt][nt][1]);
            *(float2*)(C + (size_t)(row + 8) * N + col) =
                make_float2(acc[mt][nt][2], acc[mt][nt][3]);
        }
    }
}

// ---------------- RoPE (interleaved pairs), in-place on Q and K ----------------
__global__ void rope_kernel(float* __restrict__ Q, float* __restrict__ K,
                            const float* __restrict__ cosv,
                            const float* __restrict__ sinv) {
    const int qn = S * HQ * (HD / 2);
    const int kn = S * HKV * (HD / 2);
    int idx = blockIdx.x * blockDim.x + threadIdx.x;
    if (idx < qn) {
        int i = idx & 63;
        int h = (idx >> 6) & (HQ - 1);
        int s = idx >> 11;
        float c = cosv[(s << 6) + i];
        float sn = sinv[(s << 6) + i];
        float2* p = (float2*)(Q + (size_t)s * D + h * HD) + i;
        float2 v = *p;
        *p = make_float2(v.x * c - v.y * sn, v.x * sn + v.y * c);
    } else if (idx < qn + kn) {
        int t = idx - qn;
        int i = t & 63;
        int h = (t >> 6) & (HKV - 1);
        int s = t >> 9;
        float c = cosv[(s << 6) + i];
        float sn = sinv[(s << 6) + i];
        float2* p = (float2*)(K + (size_t)s * KV_W + h * HD) + i;
        float2 v = *p;
        *p = make_float2(v.x * c - v.y * sn, v.x * sn + v.y * c);
    }
}

// ---------------- Flash attention, mma.sync fp16 (fully compensated) ----------
// BQ=BK=64. 8 warps: scores warp = 16 rows x 32 cols; PV warp = 16 rows x 64 cols.
// Scores = Qh*Kh + Qh*Kl + Ql*Kh; P = Ph+Pl; PV = Ph*Vh + Ph*Vl + Pl*Vh.
// Scale 1/sqrt(HD) applied at score-write (keeps Ql in fp16 normal range).
#define QK_STR 272 /* bytes per 128-col f16 row */
#define P_STR 144  /* bytes per 64-col f16 row */
#define PS_STR 68  /* floats per score row */
#define OFF_QH 0
#define OFF_QL 17408
#define OFF_KH 34816
#define OFF_KL 52224
#define OFF_VH 69632
#define OFF_VL 87040
#define OFF_PS 104448
#define OFF_PB 121856
#define OFF_PL 131072
#define OFF_FR 140288
#define OFF_IL 140544
#define ATTN2_SMEM 140800

__global__ __launch_bounds__(256) void attn_mma_kernel(
    const float* __restrict__ Qg, const float* __restrict__ Kg,
    const float* __restrict__ Vg,
    __nv_bfloat16* __restrict__ Oh, __nv_bfloat16* __restrict__ Ol) {
    extern __shared__ char smb[];
    const uint32_t sb = smem_u32(smb);
    const int tid = threadIdx.x, wid = tid >> 5, lane = tid & 31;
    const int h = blockIdx.y, q0 = blockIdx.x * 64, kvh = h >> 2;
    const int wm = wid & 3, wn = wid >> 2;
    const int g8 = lane >> 3, l8 = lane & 7;
    const int row = tid >> 2, lr = tid & 3;  // softmax role
    const int r0 = wm * 16 + (lane >> 2);    // c-frag row (r1 = r0+8)
    const float scale = 0.08838834764831845f;  // 1/sqrt(128)

    float* fRp = (float*)(smb + OFF_FR);
    float* iLp = (float*)(smb + OFF_IL);

    // load Q tile, fp16 hi/lo split (no pre-scale)
    for (int i = tid; i < 2048; i += 256) {
        int r = i >> 5, c4 = (i & 31) << 2;
        float4 q = *(const float4*)(Qg + (size_t)(q0 + r) * D + h * HD + c4);
        uint32_t h0, l0, h1, l1;
        split2h(q.x, q.y, h0, l0);
        split2h(q.z, q.w, h1, l1);
        *(uint2*)(smb + OFF_QH + r * QK_STR + c4 * 2) = make_uint2(h0, h1);
        *(uint2*)(smb + OFF_QL + r * QK_STR + c4 * 2) = make_uint2(l0, l1);
    }

    float m_i = -CUDART_INF_F, l_i = 0.f;
    float oacc[8][4];
#pragma unroll
    for (int nt = 0; nt < 8; nt++)
#pragma unroll
        for (int i = 0; i < 4; i++) oacc[nt][i] = 0.f;

    // ldmatrix base offsets
    const uint32_t aRow = (uint32_t)(wm * 16 + (g8 & 1) * 8 + l8);
    const uint32_t qhB = sb + OFF_QH + aRow * QK_STR;
    const uint32_t qlB = sb + OFF_QL + aRow * QK_STR;
    const uint32_t phB = sb + OFF_PB + aRow * P_STR;
    const uint32_t plB = sb + OFF_PL + aRow * P_STR;
    const uint32_t aColOfs = (uint32_t)((g8 >> 1) * 8) * 2;

    for (int k0 = 0; k0 <= q0; k0 += 64) {
        __syncthreads();  // prior iteration consumers done
        // load K and V tiles, fp16 hi/lo split (V transposed later by ldmatrix.trans)
        for (int i = tid; i < 2048; i += 256) {
            int r = i >> 5, c4 = (i & 31) << 2;
            float4 kv = *(const float4*)(Kg + (size_t)(k0 + r) * KV_W + kvh * HD + c4);
            float4 vv = *(const float4*)(Vg + (size_t)(k0 + r) * KV_W + kvh * HD + c4);
            uint32_t h0, l0, h1, l1;
            split2h(kv.x, kv.y, h0, l0);
            split2h(kv.z, kv.w, h1, l1);
            *(uint2*)(smb + OFF_KH + r * QK_STR + c4 * 2) = make_uint2(h0, h1);
            *(uint2*)(smb + OFF_KL + r * QK_STR + c4 * 2) = make_uint2(l0, l1);
            split2h(vv.x, vv.y, h0, l0);
            split2h(vv.z, vv.w, h1, l1);
            *(uint2*)(smb + OFF_VH + r * QK_STR + c4 * 2) = make_uint2(h0, h1);
            *(uint2*)(smb + OFF_VL + r * QK_STR + c4 * 2) = make_uint2(l0, l1);
        }
        __syncthreads();

        // ---- scores: S = Q K^T (Qh*Kh + Qh*Kl + Ql*Kh) ----
        float sacc[4][4];
#pragma unroll
        for (int nt = 0; nt < 4; nt++)
#pragma unroll
            for (int i = 0; i < 4; i++) sacc[nt][i] = 0.f;

#pragma unroll
        for (int ks = 0; ks < 8; ks++) {
            uint32_t aH[4], aL[4];
            uint32_t co = (uint32_t)(ks * 16) * 2 + aColOfs;
            ldm_x4(aH, qhB + co);
            ldm_x4(aL, qlB + co);
#pragma unroll
            for (int ntp = 0; ntp < 2; ntp++) {
                uint32_t bH[4], bL[4];
                uint32_t nrow = (uint32_t)(wn * 32 + ntp * 16 + (g8 >> 1) * 8 + l8);
                uint32_t kof = (uint32_t)(ks * 16 + (g8 & 1) * 8) * 2;
                ldm_x4(bH, sb + OFF_KH + nrow * QK_STR + kof);
                ldm_x4(bL, sb + OFF_KL + nrow * QK_STR + kof);
                mma16816h(sacc[2 * ntp], aH, bH);
                mma16816h(sacc[2 * ntp], aH, bL);
                mma16816h(sacc[2 * ntp], aL, bH);
                mma16816h(sacc[2 * ntp + 1], aH, bH + 2);
                mma16816h(sacc[2 * ntp + 1], aH, bL + 2);
                mma16816h(sacc[2 * ntp + 1], aL, bH + 2);
            }
        }
        // write masked+scaled scores to Ps
        {
            float* Ps = (float*)(smb + OFF_PS);
            int qr0 = q0 + r0, qr1 = qr0 + 8;
#pragma unroll
            for (int nt = 0; nt < 4; nt++) {
                int c = wn * 32 + nt * 8 + (lane & 3) * 2;
                int kc = k0 + c;
                Ps[r0 * PS_STR + c] = (kc <= qr0) ? sacc[nt][0] * scale : -CUDART_INF_F;
                Ps[r0 * PS_STR + c + 1] =
                    (kc + 1 <= qr0) ? sacc[nt][1] * scale : -CUDART_INF_F;
                Ps[(r0 + 8) * PS_STR + c] =
                    (kc <= qr1) ? sacc[nt][2] * scale : -CUDART_INF_F;
                Ps[(r0 + 8) * PS_STR + c + 1] =
                    (kc + 1 <= qr1) ? sacc[nt][3] * scale : -CUDART_INF_F;
            }
        }
        __syncthreads();

        // ---- online softmax (thread role: row, lr owns 16 cols) ----
        {
            const float* prow = (const float*)(smb + OFF_PS) + row * PS_STR + lr * 16;
            float pv[16];
            float rmax = -CUDART_INF_F;
#pragma unroll
            for (int j = 0; j < 16; j++) {
                pv[j] = prow[j];
                rmax = fmaxf(rmax, pv[j]);
            }
            rmax = fmaxf(rmax, __shfl_xor_sync(0xffffffff, rmax, 1));
            rmax = fmaxf(rmax, __shfl_xor_sync(0xffffffff, rmax, 2));
            float m_new = fmaxf(m_i, rmax);
            float rsum = 0.f;
#pragma unroll
            for (int j = 0; j < 16; j++) {
                pv[j] = __expf(pv[j] - m_new);
                rsum += pv[j];
            }
            rsum += __shfl_xor_sync(0xffffffff, rsum, 1);
            rsum += __shfl_xor_sync(0xffffffff, rsum, 2);
            float f = __expf(m_i - m_new);
            l_i = l_i * f + rsum;
            m_i = m_new;
            if (lr == 0) fRp[row] = f;
            // write P fp16 hi/lo
#pragma unroll
            for (int j = 0; j < 8; j++) {
                uint32_t hw, lw;
                split2h(pv[2 * j], pv[2 * j + 1], hw, lw);
                int po = row * P_STR + (lr * 16 + 2 * j) * 2;
                *(uint32_t*)(smb + OFF_PB + po) = hw;
                *(uint32_t*)(smb + OFF_PL + po) = lw;
            }
        }
        __syncthreads();

        // ---- PV: O = (Ph+Pl) * (Vh+Vl) less lo*lo, online rescale ----
        {
            float f0 = fRp[r0], f1 = fRp[r0 + 8];
#pragma unroll
            for (int nt = 0; nt < 8; nt++) {
                oacc[nt][0] *= f0;
                oacc[nt][1] *= f0;
                oacc[nt][2] *= f1;
                oacc[nt][3] *= f1;
            }
#pragma unroll
            for (int ks = 0; ks < 4; ks++) {
                uint32_t aP[4], aPl[4];
                uint32_t po = (uint32_t)(ks * 16) * 2 + ((uint32_t)((g8 >> 1) * 8) * 2);
                ldm_x4(aP, phB + po);
                ldm_x4(aPl, plB + po);
                uint32_t krow = (uint32_t)(ks * 16 + (g8 & 1) * 8 + l8);
#pragma unroll
                for (int ntp = 0; ntp < 4; ntp++) {
                    uint32_t bH[4], bL[4];
                    uint32_t ncol = (uint32_t)(wn * 64 + ntp * 16 + (g8 >> 1) * 8);
                    ldm_x4_t(bH, sb + OFF_VH + krow * QK_STR + ncol * 2);
                    ldm_x4_t(bL, sb + OFF_VL + krow * QK_STR + ncol * 2);
                    mma16816h(oacc[2 * ntp], aP, bH);
                    mma16816h(oacc[2 * ntp], aP, bL);
                    mma16816h(oacc[2 * ntp], aPl, bH);
                    mma16816h(oacc[2 * ntp + 1], aP, bH + 2);
                    mma16816h(oacc[2 * ntp + 1], aP, bL + 2);
                    mma16816h(oacc[2 * ntp + 1], aPl, bH + 2);
                }
            }
        }
    }

    if (lr == 0) iLp[row] = 1.f / l_i;
    __syncthreads();

    // finalize: scale by 1/l, write bf16 hi/lo directly (feeds wo GEMM)
    {
        float i0 = iLp[r0], i1 = iLp[r0 + 8];
#pragma unroll
        for (int nt = 0; nt < 8; nt++) {
            int col = h * HD + wn * 64 + nt * 8 + (lane & 3) * 2;
            size_t o0 = (size_t)(q0 + r0) * D + col;
            size_t o1 = (size_t)(q0 + r0 + 8) * D + col;
            uint32_t hh, ll;
            split2(oacc[nt][0] * i0, oacc[nt][1] * i0, hh, ll);
            *(uint32_t*)(Oh + o0) = hh;
            *(uint32_t*)(Ol + o0) = ll;
            split2(oacc[nt][2] * i1, oacc[nt][3] * i1, hh, ll);
            *(uint32_t*)(Oh + o1) = hh;
            *(uint32_t*)(Ol + o1) = ll;
        }
    }
}

// ---------------- launch ----------------
extern "C" void kernel_launch(void* const* d_in, const int* in_sizes, int n_in,
                              void* d_out, int out_size) {
    const float* x = (const float*)d_in[0];
    const float* wq = (const float*)d_in[1];
    const float* wk = (const float*)d_in[2];
    const float* wv = (const float*)d_in[3];
    const float* wo = (const float*)d_in[4];
    const float* cosv = (const float*)d_in[5];
    const float* sinv = (const float*)d_in[6];
    float* out = (float*)d_out;

    float *pQ, *pK, *pV;
    cudaGetSymbolAddress((void**)&pQ, g_Q);
    cudaGetSymbolAddress((void**)&pK, g_K);
    cudaGetSymbolAddress((void**)&pV, g_V);
    __nv_bfloat16 *pXh, *pXl, *pWqh, *pWql, *pWkh, *pWkl, *pWvh, *pWvl, *pWoh, *pWol;
    cudaGetSymbolAddress((void**)&pXh, g_Xh);
    cudaGetSymbolAddress((void**)&pXl, g_Xl);
    cudaGetSymbolAddress((void**)&pWqh, g_Wqh);
    cudaGetSymbolAddress((void**)&pWql, g_Wql);
    cudaGetSymbolAddress((void**)&pWkh, g_Wkh);
    cudaGetSymbolAddress((void**)&pWkl, g_Wkl);
    cudaGetSymbolAddress((void**)&pWvh, g_Wvh);
    cudaGetSymbolAddress((void**)&pWvl, g_Wvl);
    cudaGetSymbolAddress((void**)&pWoh, g_Woh);
    cudaGetSymbolAddress((void**)&pWol, g_Wol);

    cudaFuncSetAttribute(gemm_bf16x3_kernel,
                         cudaFuncAttributeMaxDynamicSharedMemorySize, GEMM_SMEM);
    cudaFuncSetAttribute(attn_mma_kernel,
                         cudaFuncAttributeMaxDynamicSharedMemorySize, ATTN2_SMEM);

    // x split + transposed weight splits
    {
        int n = S * D;
        xsplit_kernel<<<(n + 255) / 256, 256>>>(x, pXh, pXl, n);
    }
    wsplit_kernel<<<dim3(D / 32, D / 32), dim3(32, 8)>>>(wq, pWqh, pWql, D, D);
    wsplit_kernel<<<dim3(KV_W / 32, D / 32), dim3(32, 8)>>>(wk, pWkh, pWkl, D, KV_W);
    wsplit_kernel<<<dim3(KV_W / 32, D / 32), dim3(32, 8)>>>(wv, pWvh, pWvl, D, KV_W);
    wsplit_kernel<<<dim3(D / 32, D / 32), dim3(32, 8)>>>(wo, pWoh, pWol, D, D);

    // QKV projections (mma.sync bf16x3)
    gemm_bf16x3_kernel<<<dim3(D / 128, S / 128), 256, GEMM_SMEM>>>(
        pXh, pXl, pWqh, pWql, pQ, D, D);
    gemm_bf16x3_kernel<<<dim3(KV_W / 128, S / 128), 256, GEMM_SMEM>>>(
        pXh, pXl, pWkh, pWkl, pK, KV_W, D);
    gemm_bf16x3_kernel<<<dim3(KV_W / 128, S / 128), 256, GEMM_SMEM>>>(
        pXh, pXl, pWvh, pWvl, pV, KV_W, D);

    // RoPE on Q and K (fp32)
    {
        int total = S * HQ * (HD / 2) + S * HKV * (HD / 2);
        rope_kernel<<<(total + 255) / 256, 256>>>(pQ, pK, cosv, sinv);
    }

    // attention (mma.sync fp16, fully compensated; writes bf16 hi/lo)
    attn_mma_kernel<<<dim3(S / 64, HQ), 256, ATTN2_SMEM>>>(pQ, pK, pV, pXh, pXl);

    // output projection
    gemm_bf16x3_kernel<<<dim3(D / 128, S / 128), 256, GEMM_SMEM>>>(
        pXh, pXl, pWoh, pWol, out, D, D);
}

// round 11
// speedup vs baseline: 2.3923x; 1.0694x over previous
#include <cuda_runtime.h>
#include <cuda_bf16.h>
#include <cuda_fp16.h>
#include <math_constants.h>
#include <cstdint>
#include <cstddef>

#define S 2048
#define D 4096
#define HQ 32
#define HKV 8
#define HD 128
#define KV_W (HKV * HD) /* 1024 */
#define QD 6144         /* combined QKV output width */

// ---------------- scratch (no allocations allowed) ----------------
__device__ float g_QKV[(size_t)S * QD];  // Q | K | V fp32 (50 MB)

// bf16 hi/lo split buffers
__device__ __nv_bfloat16 g_Xh[(size_t)S * D], g_Xl[(size_t)S * D];  // x, then attn out
__device__ __nv_bfloat16 g_Wh[(size_t)QD * D], g_Wl[(size_t)QD * D];  // [Wq;Wk;Wv] T
__device__ __nv_bfloat16 g_Woh[(size_t)D * D], g_Wol[(size_t)D * D];

// pre-split fp16 K/V (2 fp16 per word)
__device__ uint32_t g_Kh16[(size_t)S * 512], g_Kl16[(size_t)S * 512];
__device__ uint32_t g_Vh16[(size_t)S * 512], g_Vl16[(size_t)S * 512];

// ---------------- mma.sync / cp.async / ldmatrix helpers ----------------
__device__ __forceinline__ uint32_t smem_u32(const void* p) {
    uint32_t a;
    asm("{ .reg .u64 t; cvta.to.shared.u64 t, %1; cvt.u32.u64 %0, t; }"
        : "=r"(a) : "l"(p));
    return a;
}
// bf16 mma (GEMMs)
__device__ __forceinline__ void mma16816(float* d, const uint32_t* a,
                                         const uint32_t* b) {
    asm volatile(
        "mma.sync.aligned.m16n8k16.row.col.f32.bf16.bf16.f32 "
        "{%0,%1,%2,%3}, {%4,%5,%6,%7}, {%8,%9}, {%0,%1,%2,%3};"
        : "+f"(d[0]), "+f"(d[1]), "+f"(d[2]), "+f"(d[3])
        : "r"(a[0]), "r"(a[1]), "r"(a[2]), "r"(a[3]), "r"(b[0]), "r"(b[1]));
}
// fp16 mma (attention)
__device__ __forceinline__ void mma16816h(float* d, const uint32_t* a,
                                          const uint32_t* b) {
    asm volatile(
        "mma.sync.aligned.m16n8k16.row.col.f32.f16.f16.f32 "
        "{%0,%1,%2,%3}, {%4,%5,%6,%7}, {%8,%9}, {%0,%1,%2,%3};"
        : "+f"(d[0]), "+f"(d[1]), "+f"(d[2]), "+f"(d[3])
        : "r"(a[0]), "r"(a[1]), "r"(a[2]), "r"(a[3]), "r"(b[0]), "r"(b[1]));
}
__device__ __forceinline__ void cp16(uint32_t sdst, const void* gsrc) {
    asm volatile("cp.async.cg.shared.global [%0], [%1], 16;"
                 :: "r"(sdst), "l"(gsrc) : "memory");
}
#define CP_COMMIT() asm volatile("cp.async.commit_group;" ::: "memory")
#define CP_WAIT1() asm volatile("cp.async.wait_group 1;" ::: "memory")
#define CP_WAIT0() asm volatile("cp.async.wait_group 0;" ::: "memory")

__device__ __forceinline__ void ldm_x4(uint32_t* r, uint32_t a) {
    asm volatile("ldmatrix.sync.aligned.m8n8.x4.shared.b16 {%0,%1,%2,%3}, [%4];"
                 : "=r"(r[0]), "=r"(r[1]), "=r"(r[2]), "=r"(r[3]) : "r"(a));
}
__device__ __forceinline__ void ldm_x4_t(uint32_t* r, uint32_t a) {
    asm volatile("ldmatrix.sync.aligned.m8n8.x4.trans.shared.b16 {%0,%1,%2,%3}, [%4];"
                 : "=r"(r[0]), "=r"(r[1]), "=r"(r[2]), "=r"(r[3]) : "r"(a));
}

// split two fp32 into packed bf16 hi / lo words (low 16 = first element)
__device__ __forceinline__ void split2(float x, float y, uint32_t& hi, uint32_t& lo) {
    __nv_bfloat16 hx = __float2bfloat16(x), hy = __float2bfloat16(y);
    __nv_bfloat16 lx = __float2bfloat16(x - __bfloat162float(hx));
    __nv_bfloat16 ly = __float2bfloat16(y - __bfloat162float(hy));
    hi = (uint32_t)__bfloat16_as_ushort(hx) | ((uint32_t)__bfloat16_as_ushort(hy) << 16);
    lo = (uint32_t)__bfloat16_as_ushort(lx) | ((uint32_t)__bfloat16_as_ushort(ly) << 16);
}
// split two fp32 into packed fp16 hi / lo words
__device__ __forceinline__ void split2h(float x, float y, uint32_t& hi, uint32_t& lo) {
    __half hx = __float2half_rn(x), hy = __float2half_rn(y);
    __half lx = __float2half_rn(x - __half2float(hx));
    __half ly = __float2half_rn(y - __half2float(hy));
    hi = (uint32_t)__half_as_ushort(hx) | ((uint32_t)__half_as_ushort(hy) << 16);
    lo = (uint32_t)__half_as_ushort(lx) | ((uint32_t)__half_as_ushort(ly) << 16);
}

// ---------------- split kernels ----------------
__global__ void xsplit_kernel(const float* __restrict__ x,
                              __nv_bfloat16* __restrict__ h,
                              __nv_bfloat16* __restrict__ l, int n) {
    int i = blockIdx.x * blockDim.x + threadIdx.x;
    if (i < n) {
        float v = x[i];
        __nv_bfloat16 hh = __float2bfloat16(v);
        h[i] = hh;
        l[i] = __float2bfloat16(v - __bfloat162float(hh));
    }
}

// w [Kdim, Ndim] fp32 -> th/tl [Ndim, Kdim] bf16 (transposed split)
__global__ void wsplit_kernel(const float* __restrict__ w,
                              __nv_bfloat16* __restrict__ th,
                              __nv_bfloat16* __restrict__ tl,
                              int Kdim, int Ndim) {
    __shared__ float t[32][33];
    int n0 = blockIdx.x * 32, k0 = blockIdx.y * 32;
    int tx = threadIdx.x, ty = threadIdx.y;  // 32 x 8
#pragma unroll
    for (int i = 0; i < 32; i += 8)
        t[ty + i][tx] = w[(size_t)(k0 + ty + i) * Ndim + n0 + tx];
    __syncthreads();
#pragma unroll
    for (int i = 0; i < 32; i += 8) {
        float v = t[tx][ty + i];
        __nv_bfloat16 h = __float2bfloat16(v);
        __nv_bfloat16 l = __float2bfloat16(v - __bfloat162float(h));
        size_t o = (size_t)(n0 + ty + i) * Kdim + k0 + tx;
        th[o] = h;
        tl[o] = l;
    }
}

// ---------------- bf16x3 mma.sync GEMM ----------------
#define COMP_BYTES (128 * 80)
#define BUF_BYTES (4 * COMP_BYTES)
#define GEMM_SMEM (2 * BUF_BYTES)

__device__ __forceinline__ void load_chunk_async(
    const __nv_bfloat16* Ah, const __nv_bfloat16* Al,
    const __nv_bfloat16* Bh, const __nv_bfloat16* Bl,
    int K, int kc, uint32_t sbuf, int tid) {
    const __nv_bfloat16* gp[4] = {Ah, Al, Bh, Bl};
#pragma unroll
    for (int comp = 0; comp < 4; comp++) {
#pragma unroll
        for (int i = 0; i < 2; i++) {
            int id = tid + (i << 8);
            int r = id >> 2, c = id & 3;
            cp16(sbuf + comp * COMP_BYTES + r * 80 + c * 16,
                 gp[comp] + (size_t)r * K + kc + c * 8);
        }
    }
}

__global__ __launch_bounds__(256) void gemm_bf16x3_kernel(
    const __nv_bfloat16* __restrict__ Ah, const __nv_bfloat16* __restrict__ Al,
    const __nv_bfloat16* __restrict__ Bh, const __nv_bfloat16* __restrict__ Bl,
    float* __restrict__ C, int N, int K) {
    extern __shared__ char smem[];
    const uint32_t sb = smem_u32(smem);
    const int tid = threadIdx.x;
    const int wid = tid >> 5, lane = tid & 31;
    const int wm = wid >> 2, wn = wid & 3;
    const int g8 = lane >> 3, l8 = lane & 7;
    const int bm = blockIdx.y << 7, bn = blockIdx.x << 7;

    const __nv_bfloat16* pAh = Ah + (size_t)bm * K;
    const __nv_bfloat16* pAl = Al + (size_t)bm * K;
    const __nv_bfloat16* pBh = Bh + (size_t)bn * K;
    const __nv_bfloat16* pBl = Bl + (size_t)bn * K;

    float acc[4][4][4];
#pragma unroll
    for (int mt = 0; mt < 4; mt++)
#pragma unroll
        for (int nt = 0; nt < 4; nt++)
#pragma unroll
            for (int i = 0; i < 4; i++) acc[mt][nt][i] = 0.f;

    const int NC = K >> 5;
    load_chunk_async(pAh, pAl, pBh, pBl, K, 0, sb, tid);
    CP_COMMIT();

    const uint32_t aOff = (uint32_t)((wm * 64 + (g8 & 1) * 8 + l8) * 80 + (g8 >> 1) * 16);
    const uint32_t bOff = (uint32_t)((wn * 32 + (g8 >> 1) * 8 + l8) * 80 + (g8 & 1) * 16);

    for (int c = 0; c < NC; c++) {
        const uint32_t buf = sb + (uint32_t)(c & 1) * BUF_BYTES;
        if (c + 1 < NC) {
            load_chunk_async(pAh, pAl, pBh, pBl, K, (c + 1) << 5,
                             sb + (uint32_t)((c + 1) & 1) * BUF_BYTES, tid);
            CP_COMMIT();
            CP_WAIT1();
        } else {
            CP_WAIT0();
        }
        __syncthreads();

#pragma unroll
        for (int ks = 0; ks < 2; ks++) {
            const uint32_t kb = (uint32_t)(ks * 32);
            uint32_t ah[4][4], al[4][4], bh[2][4], bl[2][4];
#pragma unroll
            for (int mt = 0; mt < 4; mt++) {
                uint32_t ao = buf + aOff + (uint32_t)(mt * 16 * 80) + kb;
                ldm_x4(ah[mt], ao);
                ldm_x4(al[mt], ao + COMP_BYTES);
            }
#pragma unroll
            for (int ntp = 0; ntp < 2; ntp++) {
                uint32_t bo = buf + bOff + (uint32_t)(ntp * 16 * 80) + kb;
                ldm_x4(bh[ntp], bo + 2 * COMP_BYTES);
                ldm_x4(bl[ntp], bo + 3 * COMP_BYTES);
            }
#pragma unroll
            for (int mt = 0; mt < 4; mt++)
#pragma unroll
                for (int ntp = 0; ntp < 2; ntp++) {
                    mma16816(acc[mt][2 * ntp], ah[mt], bh[ntp]);
                    mma16816(acc[mt][2 * ntp], ah[mt], bl[ntp]);
                    mma16816(acc[mt][2 * ntp], al[mt], bh[ntp]);
                    mma16816(acc[mt][2 * ntp + 1], ah[mt], bh[ntp] + 2);
                    mma16816(acc[mt][2 * ntp + 1], ah[mt], bl[ntp] + 2);
                    mma16816(acc[mt][2 * ntp + 1], al[mt], bh[ntp] + 2);
                }
        }
        __syncthreads();
    }

#pragma unroll
    for (int mt = 0; mt < 4; mt++) {
        int row = bm + wm * 64 + mt * 16 + (lane >> 2);
#pragma unroll
        for (int nt = 0; nt < 4; nt++) {
            int col = bn + wn * 32 + nt * 8 + (lane & 3) * 2;
            *(float2*)(C + (size_t)row * N + col) =
                make_float2(acc[mt][nt][0], acc[mt][nt][1]);
            *(float2*)(C + (size_t)(row + 8) * N + col) =
                make_float2(acc[mt][nt][2], acc[mt][nt][3]);
        }
    }
}

// ---------------- RoPE on Q (in g_QKV), fp32 in-place ----------------
__global__ void rope_q_kernel(float* __restrict__ QKV,
                              const float* __restrict__ cosv,
                              const float* __restrict__ sinv) {
    const int qn = S * HQ * (HD / 2);
    int idx = blockIdx.x * blockDim.x + threadIdx.x;
    if (idx < qn) {
        int i = idx & 63;
        int h = (idx >> 6) & (HQ - 1);
        int s = idx >> 11;
        float c = cosv[(s << 6) + i];
        float sn = sinv[(s << 6) + i];
        float2* p = (float2*)(QKV + (size_t)s * QD + h * HD) + i;
        float2 v = *p;
        *p = make_float2(v.x * c - v.y * sn, v.x * sn + v.y * c);
    }
}

// ---------------- K rope + fp16 hi/lo split; V fp16 hi/lo split ----------------
__global__ void kvsplit_kernel(const float* __restrict__ QKV,
                               const float* __restrict__ cosv,
                               const float* __restrict__ sinv,
                               uint32_t* __restrict__ Kh, uint32_t* __restrict__ Kl,
                               uint32_t* __restrict__ Vh, uint32_t* __restrict__ Vl) {
    const int n = S * 512;  // pairs per tensor
    int idx = blockIdx.x * blockDim.x + threadIdx.x;
    if (idx < n) {  // K with rope
        int pc = idx & 511, s = idx >> 9;
        int i = pc & 63;
        float2 v = *(const float2*)(QKV + (size_t)s * QD + 4096 + pc * 2);
        float c = cosv[(s << 6) + i], sn = sinv[(s << 6) + i];
        uint32_t hw, lw;
        split2h(v.x * c - v.y * sn, v.x * sn + v.y * c, hw, lw);
        Kh[idx] = hw;
        Kl[idx] = lw;
    } else if (idx < 2 * n) {  // V
        int t = idx - n;
        int pc = t & 511, s = t >> 9;
        float2 v = *(const float2*)(QKV + (size_t)s * QD + 5120 + pc * 2);
        uint32_t hw, lw;
        split2h(v.x, v.y, hw, lw);
        Vh[t] = hw;
        Vl[t] = lw;
    }
}

// ---------------- Flash attention, fp16 mma, pre-split K/V + double buffer ----
#define QK_STR 272 /* bytes per 128-col f16 row */
#define P_STR 144
#define PS_STR 68
#define OFF_QH 0
#define OFF_QL 17408
#define OFF_KV 34816
#define KV_STAGE 69632
#define ST_KH 0
#define ST_KL 17408
#define ST_VH 34816
#define ST_VL 52224
#define OFF_PS 174080
#define OFF_PB 191488
#define OFF_PL 200704
#define OFF_FR 209920
#define OFF_IL 210176
#define ATTN2_SMEM 210432

__device__ __forceinline__ void issue_kv(const uint32_t* const* gp, int k0, int kvh,
                                         uint32_t stage, int tid) {
#pragma unroll
    for (int a = 0; a < 4; a++)
#pragma unroll
        for (int j = 0; j < 4; j++) {
            int id = tid + (j << 8);
            int r = id >> 4, c = id & 15;
            cp16(stage + a * 17408 + r * QK_STR + c * 16,
                 gp[a] + (size_t)(k0 + r) * 512 + kvh * 64 + c * 4);
        }
}

__global__ __launch_bounds__(256) void attn_mma_kernel(
    const float* __restrict__ Qg, const uint32_t* __restrict__ Khg,
    const uint32_t* __restrict__ Klg, const uint32_t* __restrict__ Vhg,
    const uint32_t* __restrict__ Vlg,
    __nv_bfloat16* __restrict__ Oh, __nv_bfloat16* __restrict__ Ol) {
    extern __shared__ char smb[];
    const uint32_t sb = smem_u32(smb);
    const int tid = threadIdx.x, wid = tid >> 5, lane = tid & 31;
    const int h = blockIdx.y, q0 = blockIdx.x * 64, kvh = h >> 2;
    const int wm = wid & 3, wn = wid >> 2;
    const int g8 = lane >> 3, l8 = lane & 7;
    const int row = tid >> 2, lr = tid & 3;
    const int r0 = wm * 16 + (lane >> 2);
    const float scale = 0.08838834764831845f;  // 1/sqrt(128)

    float* fRp = (float*)(smb + OFF_FR);
    float* iLp = (float*)(smb + OFF_IL);

    // load Q tile, fp16 hi/lo split
    for (int i = tid; i < 2048; i += 256) {
        int r = i >> 5, c4 = (i & 31) << 2;
        float4 q = *(const float4*)(Qg + (size_t)(q0 + r) * QD + h * HD + c4);
        uint32_t h0, l0, h1, l1;
        split2h(q.x, q.y, h0, l0);
        split2h(q.z, q.w, h1, l1);
        *(uint2*)(smb + OFF_QH + r * QK_STR + c4 * 2) = make_uint2(h0, h1);
        *(uint2*)(smb + OFF_QL + r * QK_STR + c4 * 2) = make_uint2(l0, l1);
    }

    float m_i = -CUDART_INF_F, l_i = 0.f;
    float oacc[8][4];
#pragma unroll
    for (int nt = 0; nt < 8; nt++)
#pragma unroll
        for (int i = 0; i < 4; i++) oacc[nt][i] = 0.f;

    const uint32_t aRow = (uint32_t)(wm * 16 + (g8 & 1) * 8 + l8);
    const uint32_t qhB = sb + OFF_QH + aRow * QK_STR;
    const uint32_t qlB = sb + OFF_QL + aRow * QK_STR;
    const uint32_t phB = sb + OFF_PB + aRow * P_STR;
    const uint32_t plB = sb + OFF_PL + aRow * P_STR;
    const uint32_t aColOfs = (uint32_t)((g8 >> 1) * 8) * 2;

    const uint32_t* gp[4] = {Khg, Klg, Vhg, Vlg};
    // prologue: tile 0 -> stage 0
    issue_kv(gp, 0, kvh, sb + OFF_KV, tid);
    CP_COMMIT();

    for (int k0 = 0; k0 <= q0; k0 += 64) {
        const int it = k0 >> 6;
        const uint32_t stage = sb + OFF_KV + (uint32_t)(it & 1) * KV_STAGE;
        __syncthreads();  // all warps done with prev iteration (PV reads + Q stores)
        if (k0 + 64 <= q0) {
            issue_kv(gp, k0 + 64, kvh, sb + OFF_KV + (uint32_t)((it + 1) & 1) * KV_STAGE,
                     tid);
            CP_COMMIT();
            CP_WAIT1();  // current tile (it) complete
        } else {
            CP_WAIT0();
        }
        __syncthreads();  // cp.async data visible to all warps

        // ---- scores: S = Q K^T (Qh*Kh + Qh*Kl + Ql*Kh) ----
        float sacc[4][4];
#pragma unroll
        for (int nt = 0; nt < 4; nt++)
#pragma unroll
            for (int i = 0; i < 4; i++) sacc[nt][i] = 0.f;

#pragma unroll
        for (int ks = 0; ks < 8; ks++) {
            uint32_t aH[4], aL[4];
            uint32_t co = (uint32_t)(ks * 16) * 2 + aColOfs;
            ldm_x4(aH, qhB + co);
            ldm_x4(aL, qlB + co);
#pragma unroll
            for (int ntp = 0; ntp < 2; ntp++) {
                uint32_t bH[4], bL[4];
                uint32_t nrow = (uint32_t)(wn * 32 + ntp * 16 + (g8 >> 1) * 8 + l8);
                uint32_t kof = (uint32_t)(ks * 16 + (g8 & 1) * 8) * 2;
                ldm_x4(bH, stage + ST_KH + nrow * QK_STR + kof);
                ldm_x4(bL, stage + ST_KL + nrow * QK_STR + kof);
                mma16816h(sacc[2 * ntp], aH, bH);
                mma16816h(sacc[2 * ntp], aH, bL);
                mma16816h(sacc[2 * ntp], aL, bH);
                mma16816h(sacc[2 * ntp + 1], aH, bH + 2);
                mma16816h(sacc[2 * ntp + 1], aH, bL + 2);
                mma16816h(sacc[2 * ntp + 1], aL, bH + 2);
            }
        }
        // write masked+scaled scores to Ps
        {
            float* Ps = (float*)(smb + OFF_PS);
            int qr0 = q0 + r0, qr1 = qr0 + 8;
#pragma unroll
            for (int nt = 0; nt < 4; nt++) {
                int c = wn * 32 + nt * 8 + (lane & 3) * 2;
                int kc = k0 + c;
                Ps[r0 * PS_STR + c] = (kc <= qr0) ? sacc[nt][0] * scale : -CUDART_INF_F;
                Ps[r0 * PS_STR + c + 1] =
                    (kc + 1 <= qr0) ? sacc[nt][1] * scale : -CUDART_INF_F;
                Ps[(r0 + 8) * PS_STR + c] =
                    (kc <= qr1) ? sacc[nt][2] * scale : -CUDART_INF_F;
                Ps[(r0 + 8) * PS_STR + c + 1] =
                    (kc + 1 <= qr1) ? sacc[nt][3] * scale : -CUDART_INF_F;
            }
        }
        __syncthreads();

        // ---- online softmax ----
        {
            const float* prow = (const float*)(smb + OFF_PS) + row * PS_STR + lr * 16;
            float pv[16];
            float rmax = -CUDART_INF_F;
#pragma unroll
            for (int j = 0; j < 16; j++) {
                pv[j] = prow[j];
                rmax = fmaxf(rmax, pv[j]);
            }
            rmax = fmaxf(rmax, __shfl_xor_sync(0xffffffff, rmax, 1));
            rmax = fmaxf(rmax, __shfl_xor_sync(0xffffffff, rmax, 2));
            float m_new = fmaxf(m_i, rmax);
            float rsum = 0.f;
#pragma unroll
            for (int j = 0; j < 16; j++) {
                pv[j] = __expf(pv[j] - m_new);
                rsum += pv[j];
            }
            rsum += __shfl_xor_sync(0xffffffff, rsum, 1);
            rsum += __shfl_xor_sync(0xffffffff, rsum, 2);
            float f = __expf(m_i - m_new);
            l_i = l_i * f + rsum;
            m_i = m_new;
            if (lr == 0) fRp[row] = f;
#pragma unroll
            for (int j = 0; j < 8; j++) {
                uint32_t hw, lw;
                split2h(pv[2 * j], pv[2 * j + 1], hw, lw);
                int po = row * P_STR + (lr * 16 + 2 * j) * 2;
                *(uint32_t*)(smb + OFF_PB + po) = hw;
                *(uint32_t*)(smb + OFF_PL + po) = lw;
            }
        }
        __syncthreads();

        // ---- PV: O = (Ph+Pl)*(Vh+Vl) less lo*lo, online rescale ----
        {
            float f0 = fRp[r0], f1 = fRp[r0 + 8];
#pragma unroll
            for (int nt = 0; nt < 8; nt++) {
                oacc[nt][0] *= f0;
                oacc[nt][1] *= f0;
                oacc[nt][2] *= f1;
                oacc[nt][3] *= f1;
            }
#pragma unroll
            for (int ks = 0; ks < 4; ks++) {
                uint32_t aP[4], aPl[4];
                uint32_t po = (uint32_t)(ks * 16) * 2 + ((uint32_t)((g8 >> 1) * 8) * 2);
                ldm_x4(aP, phB + po);
                ldm_x4(aPl, plB + po);
                uint32_t krow = (uint32_t)(ks * 16 + (g8 & 1) * 8 + l8);
#pragma unroll
                for (int ntp = 0; ntp < 4; ntp++) {
                    uint32_t bH[4], bL[4];
                    uint32_t ncol = (uint32_t)(wn * 64 + ntp * 16 + (g8 >> 1) * 8);
                    ldm_x4_t(bH, stage + ST_VH + krow * QK_STR + ncol * 2);
                    ldm_x4_t(bL, stage + ST_VL + krow * QK_STR + ncol * 2);
                    mma16816h(oacc[2 * ntp], aP, bH);
                    mma16816h(oacc[2 * ntp], aP, bL);
                    mma16816h(oacc[2 * ntp], aPl, bH);
                    mma16816h(oacc[2 * ntp + 1], aP, bH + 2);
                    mma16816h(oacc[2 * ntp + 1], aP, bL + 2);
                    mma16816h(oacc[2 * ntp + 1], aPl, bH + 2);
                }
            }
        }
    }

    if (lr == 0) iLp[row] = 1.f / l_i;
    __syncthreads();

    // finalize: scale by 1/l, write bf16 hi/lo (feeds wo GEMM)
    {
        float i0 = iLp[r0], i1 = iLp[r0 + 8];
#pragma unroll
        for (int nt = 0; nt < 8; nt++) {
            int col = h * HD + wn * 64 + nt * 8 + (lane & 3) * 2;
            size_t o0 = (size_t)(q0 + r0) * D + col;
            size_t o1 = (size_t)(q0 + r0 + 8) * D + col;
            uint32_t hh, ll;
            split2(oacc[nt][0] * i0, oacc[nt][1] * i0, hh, ll);
            *(uint32_t*)(Oh + o0) = hh;
            *(uint32_t*)(Ol + o0) = ll;
            split2(oacc[nt][2] * i1, oacc[nt][3] * i1, hh, ll);
            *(uint32_t*)(Oh + o1) = hh;
            *(uint32_t*)(Ol + o1) = ll;
        }
    }
}

// ---------------- launch ----------------
extern "C" void kernel_launch(void* const* d_in, const int* in_sizes, int n_in,
                              void* d_out, int out_size) {
    const float* x = (const float*)d_in[0];
    const float* wq = (const float*)d_in[1];
    const float* wk = (const float*)d_in[2];
    const float* wv = (const float*)d_in[3];
    const float* wo = (const float*)d_in[4];
    const float* cosv = (const float*)d_in[5];
    const float* sinv = (const float*)d_in[6];
    float* out = (float*)d_out;

    float* pQKV;
    cudaGetSymbolAddress((void**)&pQKV, g_QKV);
    __nv_bfloat16 *pXh, *pXl, *pWh, *pWl, *pWoh, *pWol;
    cudaGetSymbolAddress((void**)&pXh, g_Xh);
    cudaGetSymbolAddress((void**)&pXl, g_Xl);
    cudaGetSymbolAddress((void**)&pWh, g_Wh);
    cudaGetSymbolAddress((void**)&pWl, g_Wl);
    cudaGetSymbolAddress((void**)&pWoh, g_Woh);
    cudaGetSymbolAddress((void**)&pWol, g_Wol);
    uint32_t *pKh, *pKl, *pVh, *pVl;
    cudaGetSymbolAddress((void**)&pKh, g_Kh16);
    cudaGetSymbolAddress((void**)&pKl, g_Kl16);
    cudaGetSymbolAddress((void**)&pVh, g_Vh16);
    cudaGetSymbolAddress((void**)&pVl, g_Vl16);

    cudaFuncSetAttribute(gemm_bf16x3_kernel,
                         cudaFuncAttributeMaxDynamicSharedMemorySize, GEMM_SMEM);
    cudaFuncSetAttribute(attn_mma_kernel,
                         cudaFuncAttributeMaxDynamicSharedMemorySize, ATTN2_SMEM);

    // x split + transposed weight splits ([Wq;Wk;Wv] combined, Wo separate)
    {
        int n = S * D;
        xsplit_kernel<<<(n + 255) / 256, 256>>>(x, pXh, pXl, n);
    }
    wsplit_kernel<<<dim3(D / 32, D / 32), dim3(32, 8)>>>(wq, pWh, pWl, D, D);
    wsplit_kernel<<<dim3(KV_W / 32, D / 32), dim3(32, 8)>>>(
        wk, pWh + (size_t)4096 * D, pWl + (size_t)4096 * D, D, KV_W);
    wsplit_kernel<<<dim3(KV_W / 32, D / 32), dim3(32, 8)>>>(
        wv, pWh + (size_t)5120 * D, pWl + (size_t)5120 * D, D, KV_W);
    wsplit_kernel<<<dim3(D / 32, D / 32), dim3(32, 8)>>>(wo, pWoh, pWol, D, D);

    // combined QKV projection (one full-chip GEMM, N=6144)
    gemm_bf16x3_kernel<<<dim3(QD / 128, S / 128), 256, GEMM_SMEM>>>(
        pXh, pXl, pWh, pWl, pQKV, QD, D);

    // RoPE on Q; K rope + fp16 pre-split; V fp16 pre-split
    {
        int qn = S * HQ * (HD / 2);
        rope_q_kernel<<<(qn + 255) / 256, 256>>>(pQKV, cosv, sinv);
        int kvn = 2 * S * 512;
        kvsplit_kernel<<<(kvn + 255) / 256, 256>>>(pQKV, cosv, sinv, pKh, pKl, pVh,
                                                   pVl);
    }

    // attention (fp16 mma, double-buffered pre-split K/V; writes bf16 hi/lo)
    attn_mma_kernel<<<dim3(S / 64, HQ), 256, ATTN2_SMEM>>>(pQKV, pKh, pKl, pVh, pVl,
                                                           pXh, pXl);

    // output projection
    gemm_bf16x3_kernel<<<dim3(D / 128, S / 128), 256, GEMM_SMEM>>>(
        pXh, pXl, pWoh, pWol, out, D, D);
}